// round 1
// baseline (speedup 1.0000x reference)
#include <cuda_runtime.h>

#define B_   16
#define C_   256
#define HW_  1024
#define LDT  68   // smem row stride (floats) for 64-wide k-chunk tiles

// Scratch (device globals — no allocation allowed)
__device__ float g_khat[B_ * HW_ * C_];   // normalized keys   [b][n][c]
__device__ float g_qhat[B_ * HW_ * C_];   // normalized queries[b][m][c]
__device__ float g_v[B_ * HW_];           // value scalars     [b][n]
__device__ float g_G[B_ * HW_];           // softmax aggregate [b][m]

// ---------------------------------------------------------------------------
// Kernel 1: projections + normalize + value scalar.
// Block = 32 positions (rows) x 256 channels. Thread c computes keys/queries
// column c for all 32 rows; weights stream from L2 (each thread reads its own
// weight row), x tile is smem-broadcast.
// ---------------------------------------------------------------------------
__global__ __launch_bounds__(256) void proj_kernel(
    const float* __restrict__ batch,
    const float* __restrict__ key_w,   const float* __restrict__ key_b,
    const float* __restrict__ query_w, const float* __restrict__ query_b,
    const float* __restrict__ value_w, const float* __restrict__ value_b)
{
    __shared__ float xs[32 * 257];
    __shared__ float inv_s[32];

    const int b   = blockIdx.x >> 5;         // 32 row-tiles per batch
    const int n0  = (blockIdx.x & 31) * 32;
    const int tid = threadIdx.x;
    const int lane = tid & 31, wrp = tid >> 5;

    // x[b, n0+r, c] = batch[b][c][n0+r]; coalesced over n
    #pragma unroll
    for (int t = 0; t < 32; t++) {
        int idx = t * 256 + tid;
        int r = idx & 31, c = idx >> 5;
        xs[r * 257 + c] = batch[(b * C_ + c) * HW_ + n0 + r];
    }
    __syncthreads();

    const int c = tid;
    float accK[32], accQ[32];
    const float kb = key_b[c], qb = query_b[c];
    #pragma unroll
    for (int r = 0; r < 32; r++) { accK[r] = kb; accQ[r] = qb; }

    const float* kwp = key_w   + c * C_;   // keys[n,c] = sum_k x[n,k]*key_w[c,k]
    const float* qwp = query_w + c * C_;
    #pragma unroll 4
    for (int k = 0; k < C_; k++) {
        float wk = __ldg(kwp + k), wq = __ldg(qwp + k);
        #pragma unroll
        for (int r = 0; r < 32; r++) {
            float xv = xs[r * 257 + k];
            accK[r] = fmaf(xv, wk, accK[r]);
            accQ[r] = fmaf(xv, wq, accQ[r]);
        }
    }

    // value scalar: warp w handles rows 4w..4w+3
    const float vb = value_b[0];
    #pragma unroll
    for (int rr = 0; rr < 4; rr++) {
        int r = wrp * 4 + rr;
        float s = 0.f;
        #pragma unroll
        for (int t = 0; t < 8; t++) {
            int k = lane + t * 32;
            s = fmaf(xs[r * 257 + k], __ldg(value_w + k), s);
        }
        #pragma unroll
        for (int o = 16; o; o >>= 1) s += __shfl_down_sync(0xFFFFFFFFu, s, o);
        if (lane == 0) g_v[b * HW_ + n0 + r] = s + vb;
    }
    __syncthreads();

    // --- normalize keys ---
    #pragma unroll
    for (int r = 0; r < 32; r++) xs[r * 257 + c] = accK[r];
    __syncthreads();
    #pragma unroll
    for (int rr = 0; rr < 4; rr++) {
        int r = wrp * 4 + rr;
        float s = 0.f;
        #pragma unroll
        for (int t = 0; t < 8; t++) { float v2 = xs[r * 257 + lane + t * 32]; s = fmaf(v2, v2, s); }
        #pragma unroll
        for (int o = 16; o; o >>= 1) s += __shfl_down_sync(0xFFFFFFFFu, s, o);
        if (lane == 0) inv_s[r] = 1.0f / fmaxf(sqrtf(s), 1e-12f);
    }
    __syncthreads();
    #pragma unroll
    for (int r = 0; r < 32; r++)
        g_khat[(b * HW_ + n0 + r) * C_ + c] = accK[r] * inv_s[r];
    __syncthreads();   // inv_s fully consumed before overwrite

    // --- normalize queries ---
    #pragma unroll
    for (int r = 0; r < 32; r++) xs[r * 257 + c] = accQ[r];
    __syncthreads();
    #pragma unroll
    for (int rr = 0; rr < 4; rr++) {
        int r = wrp * 4 + rr;
        float s = 0.f;
        #pragma unroll
        for (int t = 0; t < 8; t++) { float v2 = xs[r * 257 + lane + t * 32]; s = fmaf(v2, v2, s); }
        #pragma unroll
        for (int o = 16; o; o >>= 1) s += __shfl_down_sync(0xFFFFFFFFu, s, o);
        if (lane == 0) inv_s[r] = 1.0f / fmaxf(sqrtf(s), 1e-12f);
    }
    __syncthreads();
    #pragma unroll
    for (int r = 0; r < 32; r++)
        g_qhat[(b * HW_ + n0 + r) * C_ + c] = accQ[r] * inv_s[r];
}

// ---------------------------------------------------------------------------
// Kernel 2: fused S = k̂·q̂ᵀ GEMM + column softmax aggregation (flash-style).
// Block = (b, 64 m-columns). Loops 16 n-tiles of 64; S never materialized.
// G[b,m] = (Σ_n v[n]·exp(S[n,m])) / (Σ_n exp(S[n,m]))   (S ∈ [-1,1], no max needed)
// ---------------------------------------------------------------------------
__global__ __launch_bounds__(256) void attn_kernel()
{
    __shared__ __align__(16) float ks[64 * LDT];
    __shared__ __align__(16) float qs[64 * LDT];
    __shared__ float vs[64];

    const int b  = blockIdx.y;
    const int m0 = blockIdx.x * 64;
    const int tid = threadIdx.x;
    const int tx = tid & 15, ty = tid >> 4;

    float den[4] = {0.f, 0.f, 0.f, 0.f};
    float num[4] = {0.f, 0.f, 0.f, 0.f};

    const float* kbase = g_khat + b * HW_ * C_;
    const float* qbase = g_qhat + (b * HW_ + m0) * C_;
    const float* vbase = g_v + b * HW_;

    const int qd = tid & 15, r0 = tid >> 4;

    for (int nt = 0; nt < 16; nt++) {
        float S[4][4];
        #pragma unroll
        for (int i = 0; i < 4; i++)
            #pragma unroll
            for (int j = 0; j < 4; j++) S[i][j] = 0.f;

        #pragma unroll
        for (int kc = 0; kc < 4; kc++) {
            __syncthreads();   // previous chunk's readers done
            if (kc == 0 && tid < 64) vs[tid] = vbase[nt * 64 + tid];
            const float* gk = kbase + (nt * 64) * C_ + kc * 64;
            const float* gq = qbase + kc * 64;
            #pragma unroll
            for (int p = 0; p < 4; p++) {
                int row = r0 + p * 16;
                *(float4*)&ks[row * LDT + qd * 4] = *(const float4*)(gk + row * C_ + qd * 4);
                *(float4*)&qs[row * LDT + qd * 4] = *(const float4*)(gq + row * C_ + qd * 4);
            }
            __syncthreads();

            #pragma unroll
            for (int kk = 0; kk < 64; kk += 4) {
                float4 a[4], bq[4];
                #pragma unroll
                for (int i = 0; i < 4; i++) a[i]  = *(float4*)&ks[(ty + 16 * i) * LDT + kk];
                #pragma unroll
                for (int j = 0; j < 4; j++) bq[j] = *(float4*)&qs[(tx + 16 * j) * LDT + kk];
                #pragma unroll
                for (int i = 0; i < 4; i++)
                    #pragma unroll
                    for (int j = 0; j < 4; j++) {
                        S[i][j] = fmaf(a[i].x, bq[j].x, S[i][j]);
                        S[i][j] = fmaf(a[i].y, bq[j].y, S[i][j]);
                        S[i][j] = fmaf(a[i].z, bq[j].z, S[i][j]);
                        S[i][j] = fmaf(a[i].w, bq[j].w, S[i][j]);
                    }
            }
        }

        #pragma unroll
        for (int i = 0; i < 4; i++) {
            float vi = vs[ty + 16 * i];
            #pragma unroll
            for (int j = 0; j < 4; j++) {
                float e = __expf(S[i][j]);
                den[j] += e;
                num[j] = fmaf(vi, e, num[j]);
            }
        }
    }

    // reduce den/num across ty (alias reduction buffers onto ks: 2*1024 floats)
    __syncthreads();
    float* rd = ks;
    float* rn = ks + 1024;
    #pragma unroll
    for (int j = 0; j < 4; j++) {
        rd[ty * 64 + tx + 16 * j] = den[j];
        rn[ty * 64 + tx + 16 * j] = num[j];
    }
    __syncthreads();
    if (tid < 64) {
        float D = 0.f, N = 0.f;
        #pragma unroll
        for (int t = 0; t < 16; t++) { D += rd[t * 64 + tid]; N += rn[t * 64 + tid]; }
        g_G[b * HW_ + m0 + tid] = N / D;
    }
}

// ---------------------------------------------------------------------------
// Kernel 3: out[b,c,i,j] = 3x3 box-sum of Y[b,c,h,w] = G[b,h*32+w]*batch[b,c,h,w]
// ---------------------------------------------------------------------------
__global__ __launch_bounds__(256) void conv_kernel(
    const float* __restrict__ batch, float* __restrict__ out)
{
    __shared__ float ys[HW_];
    const int c = blockIdx.x, b = blockIdx.y;
    const float* xb = batch + (b * C_ + c) * HW_;
    const float* Gb = g_G + b * HW_;
    for (int i = threadIdx.x; i < HW_; i += 256) ys[i] = Gb[i] * xb[i];
    __syncthreads();
    float* ob = out + (b * C_ + c) * 900;
    for (int o = threadIdx.x; o < 900; o += 256) {
        int i = o / 30, j = o - i * 30;
        const float* y = ys + i * 32 + j;
        ob[o] = y[0] + y[1] + y[2] +
                y[32] + y[33] + y[34] +
                y[64] + y[65] + y[66];
    }
}

extern "C" void kernel_launch(void* const* d_in, const int* in_sizes, int n_in,
                              void* d_out, int out_size)
{
    const float* batch   = (const float*)d_in[0];
    const float* key_w   = (const float*)d_in[1];
    const float* key_b   = (const float*)d_in[2];
    const float* query_w = (const float*)d_in[3];
    const float* query_b = (const float*)d_in[4];
    const float* value_w = (const float*)d_in[5];
    const float* value_b = (const float*)d_in[6];
    // d_in[7] = local_indices (int32) — unused: the gather structure collapses
    // to a 3x3 box filter analytically.

    proj_kernel<<<512, 256>>>(batch, key_w, key_b, query_w, query_b, value_w, value_b);
    attn_kernel<<<dim3(16, 16), 256>>>();
    conv_kernel<<<dim3(256, 16), 256>>>(batch, (float*)d_out);
}

// round 2
// speedup vs baseline: 1.9425x; 1.9425x over previous
#include <cuda_runtime.h>

#define B_  16
#define C_  256
#define HW_ 1024

// ---- device scratch (no allocations allowed) ----
__device__ float g_kT[B_ * C_ * HW_];   // normalized keys,   transposed [b][c][n]
__device__ float g_qT[B_ * C_ * HW_];   // normalized queries,transposed [b][c][m]
__device__ float g_wT[C_ * 512];        // [k][m] : m<256 key_w, m>=256 query_w
__device__ float g_bias[512];
__device__ float g_v[B_ * HW_];         // value scalars
__device__ float g_G[B_ * HW_];         // softmax aggregate

typedef unsigned long long u64;

__device__ __forceinline__ u64 pack2(float x, float y) {
    u64 r; asm("mov.b64 %0,{%1,%2};" : "=l"(r) : "f"(x), "f"(y)); return r;
}
__device__ __forceinline__ void unpack2(u64 v, float &x, float &y) {
    asm("mov.b64 {%0,%1},%2;" : "=f"(x), "=f"(y) : "l"(v));
}
__device__ __forceinline__ void fma2(u64 &d, u64 a, u64 b) {
    asm("fma.rn.f32x2 %0,%1,%2,%0;" : "+l"(d) : "l"(a), "l"(b));
}

// ---------------------------------------------------------------------------
// Setup: transpose K/Q weights into [k][m] (m 0..511), pack biases.
// ---------------------------------------------------------------------------
__global__ __launch_bounds__(256) void setup_kernel(
    const float* __restrict__ kw, const float* __restrict__ qw,
    const float* __restrict__ kb, const float* __restrict__ qb)
{
    int idx = blockIdx.x * 256 + threadIdx.x;      // grid 512 -> 131072
    if (idx < 512) g_bias[idx] = (idx < 256) ? kb[idx] : qb[idx - 256];
    int k = idx >> 9, m = idx & 511;
    g_wT[idx] = (m < 256) ? kw[m * C_ + k] : qw[(m - 256) * C_ + k];
}

// ---------------------------------------------------------------------------
// Value GEMV: v[b][n] = sum_c batch[b][c][n]*vw[c] + vb
// ---------------------------------------------------------------------------
__global__ __launch_bounds__(256) void value_kernel(
    const float* __restrict__ batch, const float* __restrict__ vw,
    const float* __restrict__ vb)
{
    __shared__ float w[256];
    const int b = blockIdx.y, n = blockIdx.x * 256 + threadIdx.x;
    w[threadIdx.x] = vw[threadIdx.x];
    __syncthreads();
    const float* xb = batch + b * C_ * HW_ + n;
    float acc = vb[0];
    #pragma unroll 8
    for (int c = 0; c < 256; c++) acc = fmaf(xb[c * HW_], w[c], acc);
    g_v[b * HW_ + n] = acc;
}

// ---------------------------------------------------------------------------
// Proj GEMM (f32x2): C[n][m] = x[n][k] * W[m][k] + bias, tile 64 rows x 512 cols,
// thread 8x16 (8 col-pairs packed). Epilogue: row-normalize K|Q, store transposed.
// smem: As[2][16][64] + Bs[2][16][512]  (dynamic, 72 KB)
// ---------------------------------------------------------------------------
#define PROJ_SMEM ((2*16*64 + 2*16*512) * 4)

__global__ __launch_bounds__(256, 1) void proj_kernel(const float* __restrict__ batch)
{
    extern __shared__ float sm[];
    float* sA = sm;                 // [buf][kk][n]   buf*1024 + kk*64 + n
    float* sB = sm + 2 * 16 * 64;   // [buf][kk][m]   buf*8192 + kk*512 + m

    const int tid = threadIdx.x;
    const int tx = tid & 31, ty = tid >> 5;       // ty: 8 row groups of 8
    const int b  = blockIdx.x >> 4;
    const int n0 = (blockIdx.x & 15) * 64;

    u64 acc[8][8];
    #pragma unroll
    for (int jp = 0; jp < 8; jp++) {
        u64 bias = *(const u64*)&g_bias[2 * tx + 64 * jp];
        #pragma unroll
        for (int i = 0; i < 8; i++) acc[i][jp] = bias;
    }

    const float* aSrc = batch + b * C_ * HW_ + n0;   // [c][n]
    const int akk = tid >> 4, an4 = (tid & 15) * 4;

    // prologue: chunk 0
    *(float4*)&sA[akk * 64 + an4] = *(const float4*)(aSrc + akk * HW_ + an4);
    #pragma unroll
    for (int it = 0; it < 8; it++) {
        int idx = tid + 256 * it;
        int kk = idx >> 7, m4 = (idx & 127) * 4;
        *(float4*)&sB[kk * 512 + m4] = *(const float4*)(g_wT + kk * 512 + m4);
    }
    __syncthreads();

    for (int ch = 0; ch < 16; ch++) {
        const int cur = ch & 1, nxt = cur ^ 1;
        if (ch < 15) {
            const int kc = (ch + 1) * 16;
            *(float4*)&sA[nxt * 1024 + akk * 64 + an4] =
                *(const float4*)(aSrc + (kc + akk) * HW_ + an4);
            #pragma unroll
            for (int it = 0; it < 8; it++) {
                int idx = tid + 256 * it;
                int kk = idx >> 7, m4 = (idx & 127) * 4;
                *(float4*)&sB[nxt * 8192 + kk * 512 + m4] =
                    *(const float4*)(g_wT + (kc + kk) * 512 + m4);
            }
        }
        const float* A = sA + cur * 1024;
        const float* Bt = sB + cur * 8192;
        #pragma unroll
        for (int kk = 0; kk < 16; kk++) {
            u64 a2[8], b2[8];
            #pragma unroll
            for (int i = 0; i < 8; i++) { float av = A[kk * 64 + ty * 8 + i]; a2[i] = pack2(av, av); }
            #pragma unroll
            for (int jp = 0; jp < 8; jp++) b2[jp] = *(const u64*)&Bt[kk * 512 + 2 * tx + 64 * jp];
            #pragma unroll
            for (int i = 0; i < 8; i++)
                #pragma unroll
                for (int jp = 0; jp < 8; jp++) fma2(acc[i][jp], a2[i], b2[jp]);
        }
        __syncthreads();
    }

    // epilogue: per-row norms (K: jp<4, Q: jp>=4) via warp xor-reduce over tx
    float invK[8], invQ[8];
    #pragma unroll
    for (int i = 0; i < 8; i++) {
        float sK = 0.f, sQ = 0.f;
        #pragma unroll
        for (int jp = 0; jp < 8; jp++) {
            float lo, hi; unpack2(acc[i][jp], lo, hi);
            if (jp < 4) sK += lo * lo + hi * hi; else sQ += lo * lo + hi * hi;
        }
        #pragma unroll
        for (int o = 16; o; o >>= 1) {
            sK += __shfl_xor_sync(0xFFFFFFFFu, sK, o);
            sQ += __shfl_xor_sync(0xFFFFFFFFu, sQ, o);
        }
        invK[i] = 1.0f / fmaxf(sqrtf(sK), 1e-12f);
        invQ[i] = 1.0f / fmaxf(sqrtf(sQ), 1e-12f);
    }

    // transposed stores: column c, 8 consecutive n
    #pragma unroll
    for (int jp = 0; jp < 8; jp++) {
        float* dst = (jp < 4) ? g_kT : g_qT;
        const float* inv = (jp < 4) ? invK : invQ;
        int c0 = 2 * tx + 64 * (jp & 3);
        #pragma unroll
        for (int h = 0; h < 2; h++) {
            float vals[8];
            #pragma unroll
            for (int i = 0; i < 8; i++) {
                float lo, hi; unpack2(acc[i][jp], lo, hi);
                vals[i] = (h ? hi : lo) * inv[i];
            }
            float* p = dst + (b * C_ + c0 + h) * HW_ + n0 + ty * 8;
            *(float4*)p       = make_float4(vals[0], vals[1], vals[2], vals[3]);
            *(float4*)(p + 4) = make_float4(vals[4], vals[5], vals[6], vals[7]);
        }
    }
}

// ---------------------------------------------------------------------------
// Attention (f32x2 flash): block = 128 m-cols, loops 4 n-tiles of 256 rows.
// S[n][m] = sum_c kT[c][n]*qT[c][m]; G[m] = (Σ v[n] e^{S}) / (Σ e^{S}).
// Persistent Bs[c=256][m=128] (128 KB) + double-buffered As[2][16][256] (32 KB).
// Thread: 8 row-pairs (packed) x 8 cols.
// ---------------------------------------------------------------------------
#define ATTN_SMEM ((256*128 + 2*16*256) * 4)

__global__ __launch_bounds__(256, 1) void attn_kernel()
{
    extern __shared__ float sm[];
    float* Bs = sm;                  // [c][m] : c*128 + m
    float* As = sm + 256 * 128;      // [buf][kk][n] : buf*4096 + kk*256 + n

    const int tid = threadIdx.x;
    const int tx = tid & 15, ty = tid >> 4;        // ty: 16 groups of 16 rows
    const int b  = blockIdx.y;
    const int m0 = blockIdx.x * 128;

    // fill persistent Bs (coalesced, conflict-free)
    const float* qsrc = g_qT + b * C_ * HW_ + m0;
    #pragma unroll
    for (int it = 0; it < 32; it++) {
        int idx = tid + 256 * it;                  // 8192 float4-slots
        int c = idx >> 5, m4 = (idx & 31) * 4;
        *(float4*)&Bs[c * 128 + m4] = *(const float4*)(qsrc + c * HW_ + m4);
    }

    float den[8] = {0, 0, 0, 0, 0, 0, 0, 0};
    float num[8] = {0, 0, 0, 0, 0, 0, 0, 0};
    const float* ksrc = g_kT + b * C_ * HW_;

    for (int nt = 0; nt < 4; nt++) {
        const int nb = nt * 256;
        u64 acc[8][8];
        #pragma unroll
        for (int p = 0; p < 8; p++)
            #pragma unroll
            for (int j = 0; j < 8; j++) acc[p][j] = 0ull;

        // prologue: chunk 0
        #pragma unroll
        for (int it = 0; it < 4; it++) {
            int idx = tid + 256 * it;
            int kk = idx >> 6, n4 = (idx & 63) * 4;
            *(float4*)&As[kk * 256 + n4] = *(const float4*)(ksrc + kk * HW_ + nb + n4);
        }
        __syncthreads();

        for (int ch = 0; ch < 16; ch++) {
            const int cur = ch & 1, nxt = cur ^ 1;
            if (ch < 15) {
                const int kc = (ch + 1) * 16;
                #pragma unroll
                for (int it = 0; it < 4; it++) {
                    int idx = tid + 256 * it;
                    int kk = idx >> 6, n4 = (idx & 63) * 4;
                    *(float4*)&As[nxt * 4096 + kk * 256 + n4] =
                        *(const float4*)(ksrc + (kc + kk) * HW_ + nb + n4);
                }
            }
            const float* A = As + cur * 4096;
            const int cb = ch * 16;
            #pragma unroll
            for (int kk = 0; kk < 16; kk++) {
                u64 a2[8], b2[8];
                #pragma unroll
                for (int p = 0; p < 8; p++)
                    a2[p] = *(const u64*)&A[kk * 256 + ty * 16 + 2 * p];
                #pragma unroll
                for (int j = 0; j < 8; j++) {
                    float bv = Bs[(cb + kk) * 128 + tx + 16 * j];
                    b2[j] = pack2(bv, bv);
                }
                #pragma unroll
                for (int p = 0; p < 8; p++)
                    #pragma unroll
                    for (int j = 0; j < 8; j++) fma2(acc[p][j], a2[p], b2[j]);
            }
            __syncthreads();
        }

        // exp + accumulate (S in [-1,1] -> no max subtraction needed)
        #pragma unroll
        for (int p = 0; p < 8; p++) {
            const float2 vv = *(const float2*)(g_v + b * HW_ + nb + ty * 16 + 2 * p);
            #pragma unroll
            for (int j = 0; j < 8; j++) {
                float s0, s1; unpack2(acc[p][j], s0, s1);
                float e0 = __expf(s0), e1 = __expf(s1);
                den[j] += e0 + e1;
                num[j] = fmaf(vv.x, e0, fmaf(vv.y, e1, num[j]));
            }
        }
    }

    // cross-ty reduction of den/num (reuse As region: needs 4096 floats, have 8192)
    __syncthreads();
    float* red = As;
    #pragma unroll
    for (int j = 0; j < 8; j++) {
        red[ty * 128 + tx + 16 * j]        = den[j];
        red[2048 + ty * 128 + tx + 16 * j] = num[j];
    }
    __syncthreads();
    if (tid < 128) {
        float D = 0.f, N = 0.f;
        #pragma unroll
        for (int t = 0; t < 16; t++) { D += red[t * 128 + tid]; N += red[2048 + t * 128 + tid]; }
        g_G[b * HW_ + m0 + tid] = N / D;
    }
}

// ---------------------------------------------------------------------------
// Conv: out[b,c,i,j] = 3x3 box-sum of G[b,hw]*batch[b,c,hw]
// ---------------------------------------------------------------------------
__global__ __launch_bounds__(256) void conv_kernel(
    const float* __restrict__ batch, float* __restrict__ out)
{
    __shared__ float ys[HW_];
    const int c = blockIdx.x, b = blockIdx.y;
    const float* xb = batch + (b * C_ + c) * HW_;
    const float* Gb = g_G + b * HW_;
    for (int i = threadIdx.x; i < HW_; i += 256) ys[i] = Gb[i] * xb[i];
    __syncthreads();
    float* ob = out + (b * C_ + c) * 900;
    for (int o = threadIdx.x; o < 900; o += 256) {
        int i = o / 30, j = o - i * 30;
        const float* y = ys + i * 32 + j;
        ob[o] = y[0] + y[1] + y[2] +
                y[32] + y[33] + y[34] +
                y[64] + y[65] + y[66];
    }
}

extern "C" void kernel_launch(void* const* d_in, const int* in_sizes, int n_in,
                              void* d_out, int out_size)
{
    const float* batch   = (const float*)d_in[0];
    const float* key_w   = (const float*)d_in[1];
    const float* key_b   = (const float*)d_in[2];
    const float* query_w = (const float*)d_in[3];
    const float* query_b = (const float*)d_in[4];
    const float* value_w = (const float*)d_in[5];
    const float* value_b = (const float*)d_in[6];
    // d_in[7] = local_indices (unused: collapses analytically to 3x3 box filter)

    cudaFuncSetAttribute(proj_kernel, cudaFuncAttributeMaxDynamicSharedMemorySize, PROJ_SMEM);
    cudaFuncSetAttribute(attn_kernel, cudaFuncAttributeMaxDynamicSharedMemorySize, ATTN_SMEM);

    setup_kernel<<<512, 256>>>(key_w, query_w, key_b, query_b);
    value_kernel<<<dim3(4, 16), 256>>>(batch, value_w, value_b);
    proj_kernel<<<256, 256, PROJ_SMEM>>>(batch);
    attn_kernel<<<dim3(8, 16), 256, ATTN_SMEM>>>();
    conv_kernel<<<dim3(256, 16), 256>>>(batch, (float*)d_out);
}

// round 3
// speedup vs baseline: 1.9825x; 1.0206x over previous
#include <cuda_runtime.h>

#define B_  16
#define C_  256
#define HW_ 1024
#define NSPLIT 8

// ---- device scratch (no allocations allowed) ----
__device__ float g_kT[B_ * C_ * HW_];   // normalized keys,    [b][c][n]
__device__ float g_qT[B_ * C_ * HW_];   // normalized queries, [b][c][m]
__device__ float g_wT[C_ * 512];        // [k][m] : m<256 key_w, m>=256 query_w
__device__ float g_bias[512];
__device__ float g_v[B_ * HW_];         // value scalars
__device__ float g_G[B_ * HW_];         // softmax aggregate
__device__ float g_pd[NSPLIT * B_ * HW_];  // partial denominators
__device__ float g_pn[NSPLIT * B_ * HW_];  // partial numerators

typedef unsigned long long u64;

__device__ __forceinline__ u64 pack2(float x, float y) {
    u64 r; asm("mov.b64 %0,{%1,%2};" : "=l"(r) : "f"(x), "f"(y)); return r;
}
__device__ __forceinline__ void unpack2(u64 v, float &x, float &y) {
    asm("mov.b64 {%0,%1},%2;" : "=f"(x), "=f"(y) : "l"(v));
}
__device__ __forceinline__ void fma2(u64 &d, u64 a, u64 b) {
    asm("fma.rn.f32x2 %0,%1,%2,%0;" : "+l"(d) : "l"(a), "l"(b));
}

// ---------------------------------------------------------------------------
// Setup: transpose K/Q weights into [k][m] (m 0..511), pack biases.
// ---------------------------------------------------------------------------
__global__ __launch_bounds__(256) void setup_kernel(
    const float* __restrict__ kw, const float* __restrict__ qw,
    const float* __restrict__ kb, const float* __restrict__ qb)
{
    int idx = blockIdx.x * 256 + threadIdx.x;      // 512 blocks -> 131072
    if (idx < 512) g_bias[idx] = (idx < 256) ? kb[idx] : qb[idx - 256];
    int k = idx >> 9, m = idx & 511;
    g_wT[idx] = (m < 256) ? kw[m * C_ + k] : qw[(m - 256) * C_ + k];
}

// ---------------------------------------------------------------------------
// Value GEMV: v[b][n] = sum_c batch[b][c][n]*vw[c] + vb
// ---------------------------------------------------------------------------
__global__ __launch_bounds__(256) void value_kernel(
    const float* __restrict__ batch, const float* __restrict__ vw,
    const float* __restrict__ vb)
{
    __shared__ float w[256];
    const int b = blockIdx.y, n = blockIdx.x * 256 + threadIdx.x;
    w[threadIdx.x] = vw[threadIdx.x];
    __syncthreads();
    const float* xb = batch + b * C_ * HW_ + n;
    float acc = vb[0];
    #pragma unroll 8
    for (int c = 0; c < 256; c++) acc = fmaf(xb[c * HW_], w[c], acc);
    g_v[b * HW_ + n] = acc;
}

// ---------------------------------------------------------------------------
// Proj GEMM (f32x2): block = 64 n-rows x 256 m-cols (all of K or all of Q so the
// row-norm stays in-block). Thread: 4 consecutive rows x 8 col-pairs (32 u64).
// grid (16 ntile, 16 b, 2 half). 2 CTAs/SM. Epilogue: normalize, store [c][n].
// ---------------------------------------------------------------------------
__global__ __launch_bounds__(256, 2) void proj_kernel(const float* __restrict__ batch)
{
    __shared__ float sA[2 * 16 * 64];     // buf*1024 + kk*64  + n
    __shared__ float sB[2 * 16 * 256];    // buf*4096 + kk*256 + m

    const int tid = threadIdx.x;
    const int tx = tid & 15, ty = tid >> 4;
    const int n0 = blockIdx.x * 64;
    const int b  = blockIdx.y;
    const int mh = blockIdx.z;            // 0 = keys, 1 = queries

    u64 acc[4][8];
    #pragma unroll
    for (int j = 0; j < 8; j++) {
        u64 bias = *(const u64*)&g_bias[mh * 256 + 2 * (tx + 16 * j)];
        #pragma unroll
        for (int i = 0; i < 4; i++) acc[i][j] = bias;
    }

    const float* aSrc = batch + b * C_ * HW_ + n0;          // [c][n]
    const float* bSrc = g_wT + mh * 256;                    // [k][512]
    const int akk = tid >> 4, an4 = (tid & 15) * 4;

    // prologue: chunk 0
    *(float4*)&sA[akk * 64 + an4] = *(const float4*)(aSrc + akk * HW_ + an4);
    #pragma unroll
    for (int it = 0; it < 4; it++) {
        int idx = tid + 256 * it;                           // 1024 float4
        int kk = idx >> 6, m4 = (idx & 63) * 4;
        *(float4*)&sB[kk * 256 + m4] = *(const float4*)(bSrc + kk * 512 + m4);
    }
    __syncthreads();

    for (int ch = 0; ch < 16; ch++) {
        const int cur = ch & 1, nxt = cur ^ 1;
        if (ch < 15) {
            const int kc = (ch + 1) * 16;
            *(float4*)&sA[nxt * 1024 + akk * 64 + an4] =
                *(const float4*)(aSrc + (kc + akk) * HW_ + an4);
            #pragma unroll
            for (int it = 0; it < 4; it++) {
                int idx = tid + 256 * it;
                int kk = idx >> 6, m4 = (idx & 63) * 4;
                *(float4*)&sB[nxt * 4096 + kk * 256 + m4] =
                    *(const float4*)(bSrc + (kc + kk) * 512 + m4);
            }
        }
        const float* A = sA + cur * 1024;
        const float* Bt = sB + cur * 4096;
        #pragma unroll
        for (int kk = 0; kk < 16; kk++) {
            u64 a2[4], b2[8];
            #pragma unroll
            for (int i = 0; i < 4; i++) { float av = A[kk * 64 + ty * 4 + i]; a2[i] = pack2(av, av); }
            #pragma unroll
            for (int j = 0; j < 8; j++) b2[j] = *(const u64*)&Bt[kk * 256 + 2 * (tx + 16 * j)];
            #pragma unroll
            for (int i = 0; i < 4; i++)
                #pragma unroll
                for (int j = 0; j < 8; j++) fma2(acc[i][j], a2[i], b2[j]);
        }
        __syncthreads();
    }

    // row norms: reduce squared sums across tx (xor over low 4 lane bits)
    float inv[4];
    #pragma unroll
    for (int i = 0; i < 4; i++) {
        float s = 0.f;
        #pragma unroll
        for (int j = 0; j < 8; j++) {
            float lo, hi; unpack2(acc[i][j], lo, hi);
            s += lo * lo + hi * hi;
        }
        #pragma unroll
        for (int o = 8; o; o >>= 1) s += __shfl_xor_sync(0xFFFFFFFFu, s, o);
        inv[i] = 1.0f / fmaxf(sqrtf(s), 1e-12f);
    }

    // transposed stores: for each col c, 4 consecutive n -> one STG.128
    float* dst = (mh == 0 ? g_kT : g_qT) + b * C_ * HW_ + n0 + ty * 4;
    #pragma unroll
    for (int j = 0; j < 8; j++) {
        int c0 = 2 * (tx + 16 * j);
        float lo[4], hi[4];
        #pragma unroll
        for (int i = 0; i < 4; i++) { unpack2(acc[i][j], lo[i], hi[i]); lo[i] *= inv[i]; hi[i] *= inv[i]; }
        *(float4*)(dst + c0 * HW_)       = make_float4(lo[0], lo[1], lo[2], lo[3]);
        *(float4*)(dst + (c0 + 1) * HW_) = make_float4(hi[0], hi[1], hi[2], hi[3]);
    }
}

// ---------------------------------------------------------------------------
// Attention GEMM fragment (f32x2): block = 128 n-rows x 128 m-cols x full K=256.
// grid (8 m, 16 b, 8 nsplit) = 1024 blocks, 2 CTAs/SM. Thread: 4 row-pairs x 8 cols.
// Epilogue: e = exp(S), partial num/den -> g_pn/g_pd[nsplit].
// ---------------------------------------------------------------------------
__global__ __launch_bounds__(256, 2) void attn_kernel()
{
    __shared__ float sm[8192];            // As[2][16][128] | Bs[2][16][128]
    float* As = sm;                        // buf*2048 + kk*128 + n
    float* Bs = sm + 4096;                 // buf*2048 + kk*128 + m

    const int tid = threadIdx.x;
    const int tx = tid & 15, ty = tid >> 4;
    const int m0 = blockIdx.x * 128;
    const int b  = blockIdx.y;
    const int nz = blockIdx.z;
    const int n0 = nz * 128;

    const float* gk = g_kT + b * C_ * HW_ + n0;   // [c][n]
    const float* gq = g_qT + b * C_ * HW_ + m0;   // [c][m]

    u64 acc[4][8];
    #pragma unroll
    for (int p = 0; p < 4; p++)
        #pragma unroll
        for (int j = 0; j < 8; j++) acc[p][j] = 0ull;

    // prologue: chunk 0 (each thread: 2 float4 for As, 2 for Bs)
    #pragma unroll
    for (int it = 0; it < 2; it++) {
        int idx = tid + 256 * it;                 // 512 float4 per tile
        int kk = idx >> 5, n4 = (idx & 31) * 4;
        *(float4*)&As[kk * 128 + n4] = *(const float4*)(gk + kk * HW_ + n4);
        *(float4*)&Bs[kk * 128 + n4] = *(const float4*)(gq + kk * HW_ + n4);
    }
    __syncthreads();

    for (int ch = 0; ch < 16; ch++) {
        const int cur = ch & 1, nxt = cur ^ 1;
        if (ch < 15) {
            const int kc = (ch + 1) * 16;
            #pragma unroll
            for (int it = 0; it < 2; it++) {
                int idx = tid + 256 * it;
                int kk = idx >> 5, n4 = (idx & 31) * 4;
                *(float4*)&As[nxt * 2048 + kk * 128 + n4] = *(const float4*)(gk + (kc + kk) * HW_ + n4);
                *(float4*)&Bs[nxt * 2048 + kk * 128 + n4] = *(const float4*)(gq + (kc + kk) * HW_ + n4);
            }
        }
        const float* A = As + cur * 2048;
        const float* Bt = Bs + cur * 2048;
        #pragma unroll
        for (int kk = 0; kk < 16; kk++) {
            u64 a2[4], b2[8];
            #pragma unroll
            for (int p = 0; p < 4; p++)
                a2[p] = *(const u64*)&A[kk * 128 + 2 * (ty + 16 * p)];
            #pragma unroll
            for (int j = 0; j < 8; j++) {
                float bv = Bt[kk * 128 + tx + 16 * j];
                b2[j] = pack2(bv, bv);
            }
            #pragma unroll
            for (int p = 0; p < 4; p++)
                #pragma unroll
                for (int j = 0; j < 8; j++) fma2(acc[p][j], a2[p], b2[j]);
        }
        __syncthreads();
    }

    // exp + partial accumulate (S in [-1,1], no max subtraction needed)
    float den[8] = {0,0,0,0,0,0,0,0};
    float num[8] = {0,0,0,0,0,0,0,0};
    #pragma unroll
    for (int p = 0; p < 4; p++) {
        const float2 vv = *(const float2*)(g_v + b * HW_ + n0 + 2 * (ty + 16 * p));
        #pragma unroll
        for (int j = 0; j < 8; j++) {
            float s0, s1; unpack2(acc[p][j], s0, s1);
            float e0 = __expf(s0), e1 = __expf(s1);
            den[j] += e0 + e1;
            num[j] = fmaf(vv.x, e0, fmaf(vv.y, e1, num[j]));
        }
    }

    // reduce across ty via smem (reuse As area)
    __syncthreads();
    float* rd = sm;
    float* rn = sm + 2048;
    #pragma unroll
    for (int j = 0; j < 8; j++) {
        rd[ty * 128 + tx + 16 * j] = den[j];
        rn[ty * 128 + tx + 16 * j] = num[j];
    }
    __syncthreads();
    if (tid < 128) {
        float D = 0.f, N = 0.f;
        #pragma unroll
        for (int t = 0; t < 16; t++) { D += rd[t * 128 + tid]; N += rn[t * 128 + tid]; }
        g_pd[(nz * B_ + b) * HW_ + m0 + tid] = D;
        g_pn[(nz * B_ + b) * HW_ + m0 + tid] = N;
    }
}

// ---------------------------------------------------------------------------
// Combine partials: G = sum(num) / sum(den)
// ---------------------------------------------------------------------------
__global__ __launch_bounds__(256) void gfinal_kernel()
{
    int t = blockIdx.x * 256 + threadIdx.x;   // 64 blocks -> 16384
    float D = 0.f, N = 0.f;
    #pragma unroll
    for (int z = 0; z < NSPLIT; z++) {
        D += g_pd[z * B_ * HW_ + t];
        N += g_pn[z * B_ * HW_ + t];
    }
    g_G[t] = N / D;
}

// ---------------------------------------------------------------------------
// Conv: out[b,c,i,j] = 3x3 box-sum of G[b,hw]*batch[b,c,hw]
// ---------------------------------------------------------------------------
__global__ __launch_bounds__(256) void conv_kernel(
    const float* __restrict__ batch, float* __restrict__ out)
{
    __shared__ float ys[HW_];
    const int c = blockIdx.x, b = blockIdx.y;
    const float* xb = batch + (b * C_ + c) * HW_;
    const float* Gb = g_G + b * HW_;
    for (int i = threadIdx.x; i < HW_; i += 256) ys[i] = Gb[i] * xb[i];
    __syncthreads();
    float* ob = out + (b * C_ + c) * 900;
    for (int o = threadIdx.x; o < 900; o += 256) {
        int i = o / 30, j = o - i * 30;
        const float* y = ys + i * 32 + j;
        ob[o] = y[0] + y[1] + y[2] +
                y[32] + y[33] + y[34] +
                y[64] + y[65] + y[66];
    }
}

extern "C" void kernel_launch(void* const* d_in, const int* in_sizes, int n_in,
                              void* d_out, int out_size)
{
    const float* batch   = (const float*)d_in[0];
    const float* key_w   = (const float*)d_in[1];
    const float* key_b   = (const float*)d_in[2];
    const float* query_w = (const float*)d_in[3];
    const float* query_b = (const float*)d_in[4];
    const float* value_w = (const float*)d_in[5];
    const float* value_b = (const float*)d_in[6];
    // d_in[7] = local_indices (unused: collapses analytically to 3x3 box filter)

    setup_kernel<<<512, 256>>>(key_w, query_w, key_b, query_b);
    value_kernel<<<dim3(4, 16), 256>>>(batch, value_w, value_b);
    proj_kernel<<<dim3(16, 16, 2), 256>>>(batch);
    attn_kernel<<<dim3(8, 16, NSPLIT), 256>>>();
    gfinal_kernel<<<64, 256>>>();
    conv_kernel<<<dim3(256, 16), 256>>>(batch, (float*)d_out);
}

// round 5
// speedup vs baseline: 2.8583x; 1.4418x over previous
#include <cuda_runtime.h>
#include <cuda_bf16.h>

#define B_  16
#define C_  256
#define HW_ 1024
#define NSPLIT 8

// ---- device scratch (no allocations allowed) ----
__device__ __nv_bfloat16 g_khi[B_ * HW_ * C_];  // normalized keys,    hi  [b][n][c]
__device__ __nv_bfloat16 g_klo[B_ * HW_ * C_];  //                     lo
__device__ __nv_bfloat16 g_qhi[B_ * HW_ * C_];  // normalized queries, hi  [b][m][c]
__device__ __nv_bfloat16 g_qlo[B_ * HW_ * C_];  //                     lo
__device__ float g_wT[C_ * 512];        // [k][m] : m<256 key_w, m>=256 query_w
__device__ float g_bias[512];
__device__ float g_v[B_ * HW_];         // value scalars
__device__ float g_G[B_ * HW_];         // softmax aggregate
__device__ float g_pd[NSPLIT * B_ * HW_];  // partial denominators
__device__ float g_pn[NSPLIT * B_ * HW_];  // partial numerators

typedef unsigned int       u32;
typedef unsigned long long u64;

__device__ __forceinline__ u64 pack2(float x, float y) {
    u64 r; asm("mov.b64 %0,{%1,%2};" : "=l"(r) : "f"(x), "f"(y)); return r;
}
__device__ __forceinline__ void unpack2(u64 v, float &x, float &y) {
    asm("mov.b64 {%0,%1},%2;" : "=f"(x), "=f"(y) : "l"(v));
}
__device__ __forceinline__ void fma2(u64 &d, u64 a, u64 b) {
    asm("fma.rn.f32x2 %0,%1,%2,%0;" : "+l"(d) : "l"(a), "l"(b));
}
__device__ __forceinline__ u32 smem_u32(const void* p) {
    u32 a; asm("{ .reg .u64 t; cvta.to.shared.u64 t,%1; cvt.u32.u64 %0,t; }" : "=r"(a) : "l"(p));
    return a;
}
__device__ __forceinline__ void ldmx4(u32* r, u32 addr) {
    asm volatile("ldmatrix.sync.aligned.m8n8.x4.shared.b16 {%0,%1,%2,%3},[%4];"
                 : "=r"(r[0]), "=r"(r[1]), "=r"(r[2]), "=r"(r[3]) : "r"(addr));
}
__device__ __forceinline__ void mma_bf16(float* c, const u32* a, u32 b0, u32 b1) {
    asm volatile("mma.sync.aligned.m16n8k16.row.col.f32.bf16.bf16.f32 "
                 "{%0,%1,%2,%3},{%4,%5,%6,%7},{%8,%9},{%0,%1,%2,%3};"
                 : "+f"(c[0]), "+f"(c[1]), "+f"(c[2]), "+f"(c[3])
                 : "r"(a[0]), "r"(a[1]), "r"(a[2]), "r"(a[3]), "r"(b0), "r"(b1));
}
#define CP16(sa, ga) asm volatile("cp.async.cg.shared.global [%0],[%1],16;" :: "r"(sa), "l"(ga))
#define CP_COMMIT()  asm volatile("cp.async.commit_group;" ::: "memory")
#define CP_WAIT(N)   asm volatile("cp.async.wait_group %0;" :: "n"(N) : "memory")

// exp(s) for s in [-1,1]: degree-8 Taylor (max rel err ~7.5e-6), FMA pipe only.
__device__ __forceinline__ float exp_poly(float s) {
    float e = fmaf(2.4801587e-5f, s, 1.9841270e-4f);
    e = fmaf(e, s, 1.3888889e-3f);
    e = fmaf(e, s, 8.3333333e-3f);
    e = fmaf(e, s, 4.1666667e-2f);
    e = fmaf(e, s, 0.16666667f);
    e = fmaf(e, s, 0.5f);
    e = fmaf(e, s, 1.0f);
    e = fmaf(e, s, 1.0f);
    return e;
}

// ---------------------------------------------------------------------------
// Setup: transpose K/Q weights into [k][m] (m 0..511), pack biases.
// ---------------------------------------------------------------------------
__global__ __launch_bounds__(256) void setup_kernel(
    const float* __restrict__ kw, const float* __restrict__ qw,
    const float* __restrict__ kb, const float* __restrict__ qb)
{
    int idx = blockIdx.x * 256 + threadIdx.x;
    if (idx < 512) g_bias[idx] = (idx < 256) ? kb[idx] : qb[idx - 256];
    int k = idx >> 9, m = idx & 511;
    g_wT[idx] = (m < 256) ? kw[m * C_ + k] : qw[(m - 256) * C_ + k];
}

// ---------------------------------------------------------------------------
// Value GEMV: v[b][n] = sum_c batch[b][c][n]*vw[c] + vb
// ---------------------------------------------------------------------------
__global__ __launch_bounds__(256) void value_kernel(
    const float* __restrict__ batch, const float* __restrict__ vw,
    const float* __restrict__ vb)
{
    __shared__ float w[256];
    const int b = blockIdx.y, n = blockIdx.x * 256 + threadIdx.x;
    w[threadIdx.x] = vw[threadIdx.x];
    __syncthreads();
    const float* xb = batch + b * C_ * HW_ + n;
    float acc = vb[0];
    #pragma unroll 8
    for (int c = 0; c < 256; c++) acc = fmaf(xb[c * HW_], w[c], acc);
    g_v[b * HW_ + n] = acc;
}

// ---------------------------------------------------------------------------
// Proj GEMM (f32x2): block = 64 n-rows x 256 m-cols (all of K or all of Q).
// Epilogue: normalize rows, split into bf16 hi/lo, store K-major [b][n][c].
// ---------------------------------------------------------------------------
__global__ __launch_bounds__(256, 2) void proj_kernel(const float* __restrict__ batch)
{
    __shared__ float sA[2 * 16 * 64];
    __shared__ float sB[2 * 16 * 256];

    const int tid = threadIdx.x;
    const int tx = tid & 15, ty = tid >> 4;
    const int n0 = blockIdx.x * 64;
    const int b  = blockIdx.y;
    const int mh = blockIdx.z;            // 0 = keys, 1 = queries

    u64 acc[4][8];
    #pragma unroll
    for (int j = 0; j < 8; j++) {
        u64 bias = *(const u64*)&g_bias[mh * 256 + 2 * (tx + 16 * j)];
        #pragma unroll
        for (int i = 0; i < 4; i++) acc[i][j] = bias;
    }

    const float* aSrc = batch + b * C_ * HW_ + n0;
    const float* bSrc = g_wT + mh * 256;
    const int akk = tid >> 4, an4 = (tid & 15) * 4;

    *(float4*)&sA[akk * 64 + an4] = *(const float4*)(aSrc + akk * HW_ + an4);
    #pragma unroll
    for (int it = 0; it < 4; it++) {
        int idx = tid + 256 * it;
        int kk = idx >> 6, m4 = (idx & 63) * 4;
        *(float4*)&sB[kk * 256 + m4] = *(const float4*)(bSrc + kk * 512 + m4);
    }
    __syncthreads();

    for (int ch = 0; ch < 16; ch++) {
        const int cur = ch & 1, nxt = cur ^ 1;
        if (ch < 15) {
            const int kc = (ch + 1) * 16;
            *(float4*)&sA[nxt * 1024 + akk * 64 + an4] =
                *(const float4*)(aSrc + (kc + akk) * HW_ + an4);
            #pragma unroll
            for (int it = 0; it < 4; it++) {
                int idx = tid + 256 * it;
                int kk = idx >> 6, m4 = (idx & 63) * 4;
                *(float4*)&sB[nxt * 4096 + kk * 256 + m4] =
                    *(const float4*)(bSrc + (kc + kk) * 512 + m4);
            }
        }
        const float* A = sA + cur * 1024;
        const float* Bt = sB + cur * 4096;
        #pragma unroll
        for (int kk = 0; kk < 16; kk++) {
            u64 a2[4], b2[8];
            #pragma unroll
            for (int i = 0; i < 4; i++) { float av = A[kk * 64 + ty * 4 + i]; a2[i] = pack2(av, av); }
            #pragma unroll
            for (int j = 0; j < 8; j++) b2[j] = *(const u64*)&Bt[kk * 256 + 2 * (tx + 16 * j)];
            #pragma unroll
            for (int i = 0; i < 4; i++)
                #pragma unroll
                for (int j = 0; j < 8; j++) fma2(acc[i][j], a2[i], b2[j]);
        }
        __syncthreads();
    }

    float inv[4];
    #pragma unroll
    for (int i = 0; i < 4; i++) {
        float s = 0.f;
        #pragma unroll
        for (int j = 0; j < 8; j++) {
            float lo, hi; unpack2(acc[i][j], lo, hi);
            s += lo * lo + hi * hi;
        }
        #pragma unroll
        for (int o = 8; o; o >>= 1) s += __shfl_xor_sync(0xFFFFFFFFu, s, o);
        inv[i] = 1.0f / fmaxf(sqrtf(s), 1e-12f);
    }

    __nv_bfloat16* Hh = mh ? g_qhi : g_khi;
    __nv_bfloat16* Hl = mh ? g_qlo : g_klo;
    #pragma unroll
    for (int i = 0; i < 4; i++) {
        int n = n0 + ty * 4 + i;
        __nv_bfloat162* dh = (__nv_bfloat162*)(Hh + (size_t)(b * HW_ + n) * C_);
        __nv_bfloat162* dl = (__nv_bfloat162*)(Hl + (size_t)(b * HW_ + n) * C_);
        #pragma unroll
        for (int j = 0; j < 8; j++) {
            float lo, hi; unpack2(acc[i][j], lo, hi);
            float v0 = lo * inv[i], v1 = hi * inv[i];
            __nv_bfloat16 h0 = __float2bfloat16(v0), h1 = __float2bfloat16(v1);
            __nv_bfloat16 l0 = __float2bfloat16(v0 - __bfloat162float(h0));
            __nv_bfloat16 l1 = __float2bfloat16(v1 - __bfloat162float(h1));
            dh[tx + 16 * j] = __halves2bfloat162(h0, h1);
            dl[tx + 16 * j] = __halves2bfloat162(l0, l1);
        }
    }
}

// ---------------------------------------------------------------------------
// Attention via mma.sync (HMMA bf16): block = 128n x 128m x K=256.
// hi/lo split: S = Ah.Bh + Ah.Bl + Al.Bh (err ~1.5e-5). 8 warps (2n x 4m),
// warp tile 64x32, m16n8k16 atoms. cp.async double-buffered k-chunks of 32.
// Epilogue: polynomial exp + shfl column reduce -> partial num/den.
// smem tile: 128 rows x 80B (32 bf16 + 16B pad) -> conflict-free ldmatrix.
// ---------------------------------------------------------------------------
#define TILE_B  10240            // one 128x40-bf16 tile
#define BUF_B   (4 * TILE_B)     // Ah,Al,Bh,Bl
#define ATTN_SMEM (2 * BUF_B)    // 80 KB double buffer

__global__ __launch_bounds__(256, 2) void attn_kernel()
{
    extern __shared__ __align__(16) char sm[];
    const u32 smb = smem_u32(sm);
    const int tid = threadIdx.x, lane = tid & 31, wid = tid >> 5;
    const int wn = wid >> 2, wm = wid & 3;
    const int m0 = blockIdx.x * 128, b = blockIdx.y, nz = blockIdx.z;
    const int n0 = nz * 128;

    // cp.async per-thread addressing: 512 16B segs per tile, 2 per thread
    const char* srcA[2] = { (const char*)(g_khi + (size_t)(b * HW_ + n0) * C_),
                            (const char*)(g_klo + (size_t)(b * HW_ + n0) * C_) };
    const char* srcB[2] = { (const char*)(g_qhi + (size_t)(b * HW_ + m0) * C_),
                            (const char*)(g_qlo + (size_t)(b * HW_ + m0) * C_) };

    auto load_chunk = [&](int ch, int buf) {
        const u32 dbase = smb + buf * BUF_B;
        #pragma unroll
        for (int it = 0; it < 2; it++) {
            int t = tid + 256 * it;
            int row = t >> 2, seg = t & 3;
            u32 doff = row * 80 + seg * 16;
            u64 soff = (u64)row * 512 + ch * 64 + seg * 16;
            CP16(dbase + 0 * TILE_B + doff, srcA[0] + soff);
            CP16(dbase + 1 * TILE_B + doff, srcA[1] + soff);
            CP16(dbase + 2 * TILE_B + doff, srcB[0] + soff);
            CP16(dbase + 3 * TILE_B + doff, srcB[1] + soff);
        }
        CP_COMMIT();
    };

    // ldmatrix per-thread bases (q = matrix idx, r = row within 8)
    const int q = lane >> 3, r = lane & 7;
    const u32 aB = smb + (wn * 64 + (q & 1) * 8 + r) * 80 + (q >> 1) * 16;           // Ah
    const u32 bB = smb + 2 * TILE_B + (wm * 32 + (q & 1) * 8 + r) * 80 + (q >> 1) * 16; // Bh

    float C[4][4][4];
    #pragma unroll
    for (int i = 0; i < 4; i++)
        #pragma unroll
        for (int j = 0; j < 4; j++)
            #pragma unroll
            for (int k = 0; k < 4; k++) C[i][j][k] = 0.f;

    // v values for this thread's rows
    float v0[4], v1[4];
    #pragma unroll
    for (int ni = 0; ni < 4; ni++) {
        int nr = n0 + wn * 64 + ni * 16 + (lane >> 2);
        v0[ni] = g_v[b * HW_ + nr];
        v1[ni] = g_v[b * HW_ + nr + 8];
    }

    load_chunk(0, 0);
    for (int ch = 0; ch < 8; ch++) {
        const int buf = ch & 1;
        if (ch < 7) { load_chunk(ch + 1, buf ^ 1); CP_WAIT(1); }
        else        { CP_WAIT(0); }
        __syncthreads();

        const u32 A0 = aB + buf * BUF_B;
        const u32 B0 = bB + buf * BUF_B;
        #pragma unroll
        for (int ks = 0; ks < 2; ks++) {
            u32 ah[4][4], al[4][4], bh[2][4], bl[2][4];
            #pragma unroll
            for (int ni = 0; ni < 4; ni++) {
                ldmx4(ah[ni], A0 + ks * 32 + ni * 16 * 80);
                ldmx4(al[ni], A0 + ks * 32 + ni * 16 * 80 + TILE_B);
            }
            #pragma unroll
            for (int p = 0; p < 2; p++) {
                ldmx4(bh[p], B0 + ks * 32 + p * 16 * 80);
                ldmx4(bl[p], B0 + ks * 32 + p * 16 * 80 + TILE_B);
            }
            #pragma unroll
            for (int ni = 0; ni < 4; ni++)
                #pragma unroll
                for (int mj = 0; mj < 4; mj++) {
                    const int p = mj >> 1, w = mj & 1;
                    mma_bf16(C[ni][mj], ah[ni], bh[p][w], bh[p][w + 2]);
                    mma_bf16(C[ni][mj], ah[ni], bl[p][w], bl[p][w + 2]);
                    mma_bf16(C[ni][mj], al[ni], bh[p][w], bh[p][w + 2]);
                }
        }
        __syncthreads();
    }

    // epilogue: exp + column sums. c0,c1: row g cols 2t,2t+1; c2,c3: row g+8.
    float dsum[4][2] = {}, nsum[4][2] = {};
    #pragma unroll
    for (int ni = 0; ni < 4; ni++)
        #pragma unroll
        for (int mj = 0; mj < 4; mj++) {
            float e0 = exp_poly(C[ni][mj][0]);
            float e1 = exp_poly(C[ni][mj][1]);
            float e2 = exp_poly(C[ni][mj][2]);
            float e3 = exp_poly(C[ni][mj][3]);
            dsum[mj][0] += e0 + e2;
            dsum[mj][1] += e1 + e3;
            nsum[mj][0] = fmaf(v0[ni], e0, fmaf(v1[ni], e2, nsum[mj][0]));
            nsum[mj][1] = fmaf(v0[ni], e1, fmaf(v1[ni], e3, nsum[mj][1]));
        }
    #pragma unroll
    for (int mj = 0; mj < 4; mj++)
        #pragma unroll
        for (int h = 0; h < 2; h++) {
            #pragma unroll
            for (int msk = 4; msk <= 16; msk <<= 1) {
                dsum[mj][h] += __shfl_xor_sync(0xFFFFFFFFu, dsum[mj][h], msk);
                nsum[mj][h] += __shfl_xor_sync(0xFFFFFFFFu, nsum[mj][h], msk);
            }
        }

    float* redD = (float*)sm;          // [2 wn][128]
    float* redN = redD + 256;
    if (lane < 4) {
        #pragma unroll
        for (int mj = 0; mj < 4; mj++)
            #pragma unroll
            for (int h = 0; h < 2; h++) {
                int col = wm * 32 + mj * 8 + lane * 2 + h;
                redD[wn * 128 + col] = dsum[mj][h];
                redN[wn * 128 + col] = nsum[mj][h];
            }
    }
    __syncthreads();
    if (tid < 128) {
        g_pd[(size_t)(nz * B_ + b) * HW_ + m0 + tid] = redD[tid] + redD[128 + tid];
        g_pn[(size_t)(nz * B_ + b) * HW_ + m0 + tid] = redN[tid] + redN[128 + tid];
    }
}

// ---------------------------------------------------------------------------
// Combine partials: G = sum(num) / sum(den)
// ---------------------------------------------------------------------------
__global__ __launch_bounds__(256) void gfinal_kernel()
{
    int t = blockIdx.x * 256 + threadIdx.x;
    float D = 0.f, N = 0.f;
    #pragma unroll
    for (int z = 0; z < NSPLIT; z++) {
        D += g_pd[z * B_ * HW_ + t];
        N += g_pn[z * B_ * HW_ + t];
    }
    g_G[t] = N / D;
}

// ---------------------------------------------------------------------------
// Conv: out[b,c,i,j] = 3x3 box-sum of G[b,hw]*batch[b,c,hw]
// ---------------------------------------------------------------------------
__global__ __launch_bounds__(256) void conv_kernel(
    const float* __restrict__ batch, float* __restrict__ out)
{
    __shared__ float ys[HW_];
    const int c = blockIdx.x, b = blockIdx.y;
    const float* xb = batch + (b * C_ + c) * HW_;
    const float* Gb = g_G + b * HW_;
    for (int i = threadIdx.x; i < HW_; i += 256) ys[i] = Gb[i] * xb[i];
    __syncthreads();
    float* ob = out + (b * C_ + c) * 900;
    for (int o = threadIdx.x; o < 900; o += 256) {
        int i = o / 30, j = o - i * 30;
        const float* y = ys + i * 32 + j;
        ob[o] = y[0] + y[1] + y[2] +
                y[32] + y[33] + y[34] +
                y[64] + y[65] + y[66];
    }
}

extern "C" void kernel_launch(void* const* d_in, const int* in_sizes, int n_in,
                              void* d_out, int out_size)
{
    const float* batch   = (const float*)d_in[0];
    const float* key_w   = (const float*)d_in[1];
    const float* key_b   = (const float*)d_in[2];
    const float* query_w = (const float*)d_in[3];
    const float* query_b = (const float*)d_in[4];
    const float* value_w = (const float*)d_in[5];
    const float* value_b = (const float*)d_in[6];
    // d_in[7] = local_indices (unused: collapses analytically to 3x3 box filter)

    cudaFuncSetAttribute(attn_kernel, cudaFuncAttributeMaxDynamicSharedMemorySize, ATTN_SMEM);

    setup_kernel<<<512, 256>>>(key_w, query_w, key_b, query_b);
    value_kernel<<<dim3(4, 16), 256>>>(batch, value_w, value_b);
    proj_kernel<<<dim3(16, 16, 2), 256>>>(batch);
    attn_kernel<<<dim3(8, 16, NSPLIT), 256, ATTN_SMEM>>>();
    gfinal_kernel<<<64, 256>>>();
    conv_kernel<<<dim3(256, 16), 256>>>(batch, (float*)d_out);
}

// round 7
// speedup vs baseline: 3.2922x; 1.1518x over previous
#include <cuda_runtime.h>
#include <cuda_bf16.h>

#define B_  16
#define C_  256
#define HW_ 1024
#define NSPLIT 8

// ---- device scratch (no allocations allowed) ----
__device__ __nv_bfloat16 g_xhi[B_ * HW_ * C_];  // x transposed [b][n][c], hi
__device__ __nv_bfloat16 g_xlo[B_ * HW_ * C_];  //                         lo
__device__ __nv_bfloat16 g_whi[512 * C_];       // weights [m][k]: m<256 K, else Q
__device__ __nv_bfloat16 g_wlo[512 * C_];
__device__ __nv_bfloat16 g_khi[B_ * HW_ * C_];  // normalized keys hi  [b][n][c]
__device__ __nv_bfloat16 g_klo[B_ * HW_ * C_];
__device__ __nv_bfloat16 g_qhi[B_ * HW_ * C_];  // normalized queries  [b][m][c]
__device__ __nv_bfloat16 g_qlo[B_ * HW_ * C_];
__device__ float g_bias[512];
__device__ float g_v[B_ * HW_];            // value scalars
__device__ float g_G[B_ * HW_];            // softmax aggregate
__device__ float g_pd[NSPLIT * B_ * HW_];  // partial denominators
__device__ float g_pn[NSPLIT * B_ * HW_];  // partial numerators

typedef unsigned int       u32;
typedef unsigned long long u64;

__device__ __forceinline__ u32 smem_u32(const void* p) {
    u32 a; asm("{ .reg .u64 t; cvta.to.shared.u64 t,%1; cvt.u32.u64 %0,t; }" : "=r"(a) : "l"(p));
    return a;
}
__device__ __forceinline__ void ldmx4(u32* r, u32 addr) {
    asm volatile("ldmatrix.sync.aligned.m8n8.x4.shared.b16 {%0,%1,%2,%3},[%4];"
                 : "=r"(r[0]), "=r"(r[1]), "=r"(r[2]), "=r"(r[3]) : "r"(addr));
}
__device__ __forceinline__ void mma_bf16(float* c, const u32* a, u32 b0, u32 b1) {
    asm volatile("mma.sync.aligned.m16n8k16.row.col.f32.bf16.bf16.f32 "
                 "{%0,%1,%2,%3},{%4,%5,%6,%7},{%8,%9},{%0,%1,%2,%3};"
                 : "+f"(c[0]), "+f"(c[1]), "+f"(c[2]), "+f"(c[3])
                 : "r"(a[0]), "r"(a[1]), "r"(a[2]), "r"(a[3]), "r"(b0), "r"(b1));
}
#define CP16(sa, ga) asm volatile("cp.async.cg.shared.global [%0],[%1],16;" :: "r"(sa), "l"(ga))
#define CP_COMMIT()  asm volatile("cp.async.commit_group;" ::: "memory")
#define CP_WAIT(N)   asm volatile("cp.async.wait_group %0;" :: "n"(N) : "memory")

__device__ __forceinline__ void split_pair(float a, float b, u32 &hi, u32 &lo) {
    __nv_bfloat16 h0 = __float2bfloat16(a), h1 = __float2bfloat16(b);
    __nv_bfloat16 l0 = __float2bfloat16(a - __bfloat162float(h0));
    __nv_bfloat16 l1 = __float2bfloat16(b - __bfloat162float(h1));
    __nv_bfloat162 th = __halves2bfloat162(h0, h1), tl = __halves2bfloat162(l0, l1);
    hi = *(u32*)&th; lo = *(u32*)&tl;
}

// exp(s) for s in [-1,1]: degree-8 Taylor (max rel err ~7.5e-6), FMA pipe only.
__device__ __forceinline__ float exp_poly(float s) {
    float e = fmaf(2.4801587e-5f, s, 1.9841270e-4f);
    e = fmaf(e, s, 1.3888889e-3f);
    e = fmaf(e, s, 8.3333333e-3f);
    e = fmaf(e, s, 4.1666667e-2f);
    e = fmaf(e, s, 0.16666667f);
    e = fmaf(e, s, 0.5f);
    e = fmaf(e, s, 1.0f);
    e = fmaf(e, s, 1.0f);
    return e;
}

// ---------------------------------------------------------------------------
// Setup: weights bf16 hi/lo [m][k] (m 0..511: K then Q), biases fp32.
// ---------------------------------------------------------------------------
__global__ __launch_bounds__(256) void setup_kernel(
    const float* __restrict__ kw, const float* __restrict__ qw,
    const float* __restrict__ kb, const float* __restrict__ qb)
{
    int idx = blockIdx.x * 256 + threadIdx.x;      // 512x256 = 131072
    if (idx < 512) g_bias[idx] = (idx < 256) ? kb[idx] : qb[idx - 256];
    int m = idx >> 8, k = idx & 255;
    float w = (m < 256) ? kw[m * C_ + k] : qw[(m - 256) * C_ + k];
    __nv_bfloat16 h = __float2bfloat16(w);
    g_whi[idx] = h;
    g_wlo[idx] = __float2bfloat16(w - __bfloat162float(h));
}

// ---------------------------------------------------------------------------
// xsplit: transpose batch [b][c][n] -> bf16 hi/lo [b][n][c], fold value GEMV.
// Block = (32 n) x (all 256 c). smem [j][c] with per-32 skew (conflict-free).
// ---------------------------------------------------------------------------
__global__ __launch_bounds__(256) void xsplit_kernel(
    const float* __restrict__ batch, const float* __restrict__ vw,
    const float* __restrict__ vb)
{
    __shared__ float xs[32 * 264 + 8];   // addr = j*264 + c + (c>>5)
    __shared__ float wsm[256];
    __shared__ float vp[256];
    const int b = blockIdx.y, n0 = blockIdx.x * 32;
    const int tid = threadIdx.x;
    wsm[tid] = vw[tid];

    #pragma unroll
    for (int it = 0; it < 32; it++) {
        int idx = it * 256 + tid;
        int c = idx >> 5, j = idx & 31;
        xs[j * 264 + c + (c >> 5)] = batch[(b * C_ + c) * HW_ + n0 + j];
    }
    __syncthreads();

    // value partials: warp w sums c in [32w, 32w+32) for position j
    {
        const int w = tid >> 5, j = tid & 31;
        float p = 0.f;
        #pragma unroll
        for (int cc = 0; cc < 32; cc++) {
            int c = w * 32 + cc;
            p = fmaf(xs[j * 264 + c + (c >> 5)], wsm[c], p);
        }
        vp[w * 32 + j] = p;
    }
    __syncthreads();
    if (tid < 32) {
        float s = vb[0];
        #pragma unroll
        for (int w = 0; w < 8; w++) s += vp[w * 32 + tid];
        g_v[b * HW_ + n0 + tid] = s;
    }

    // transpose write: thread = (n' = tid>>3, seg = tid&7), 32 c's per seg
    const int np = tid >> 3, seg = tid & 7, c0 = seg * 32;
    u32 h[16], l[16];
    #pragma unroll
    for (int i = 0; i < 16; i++) {
        int c = c0 + 2 * i;
        float a = xs[np * 264 + c + (c >> 5)];
        float d = xs[np * 264 + c + 1 + ((c + 1) >> 5)];
        split_pair(a, d, h[i], l[i]);
    }
    u32* dh = (u32*)(g_xhi + (size_t)(b * HW_ + n0 + np) * C_) + seg * 16;
    u32* dl = (u32*)(g_xlo + (size_t)(b * HW_ + n0 + np) * C_) + seg * 16;
    #pragma unroll
    for (int k = 0; k < 4; k++) {
        *(uint4*)(dh + 4 * k) = make_uint4(h[4*k], h[4*k+1], h[4*k+2], h[4*k+3]);
        *(uint4*)(dl + 4 * k) = make_uint4(l[4*k], l[4*k+1], l[4*k+2], l[4*k+3]);
    }
}

// ---------------------------------------------------------------------------
// Proj via mma.sync (bf16 hi/lo, 3 products): block = 64n x 256m x K=256.
// grid (16 ntile, 16 b, 2 mh) = 512 blocks, 512 threads (16 warps = 2n x 8m,
// warp tile 32x32). Epilogue: +bias, row norms, normalize, bf16 hi/lo store.
// smem/stage: Ah,Al[64x80B] + Bh,Bl[256x80B] = 51200 B, double buffered.
// ---------------------------------------------------------------------------
#define PJ_A    5120
#define PJ_B    20480
#define PJ_STG  (2*PJ_A + 2*PJ_B)    // 51200
#define PROJ_SMEM (2 * PJ_STG)       // 102400

__global__ __launch_bounds__(512, 1) void proj_kernel()
{
    extern __shared__ __align__(16) char sm[];
    const u32 smb = smem_u32(sm);
    const int tid = threadIdx.x, lane = tid & 31, wid = tid >> 5;
    const int wn = wid >> 3, wm = wid & 7;
    const int n0 = blockIdx.x * 64;
    const int b  = blockIdx.y;
    const int mh = blockIdx.z;
    const int m0 = mh * 256;

    const char* srcAh = (const char*)(g_xhi + (size_t)(b * HW_ + n0) * C_);
    const char* srcAl = (const char*)(g_xlo + (size_t)(b * HW_ + n0) * C_);
    const char* srcBh = (const char*)(g_whi + (size_t)m0 * C_);
    const char* srcBl = (const char*)(g_wlo + (size_t)m0 * C_);

    auto load_chunk = [&](int ch, int buf) {
        const u32 dbase = smb + buf * PJ_STG;
        #pragma unroll
        for (int it = 0; it < 5; it++) {
            int s = it * 512 + tid;
            if (s < 512) {
                int hl = s >> 8, u = s & 255;
                int r = u >> 2, q = u & 3;
                CP16(dbase + hl * PJ_A + r * 80 + q * 16,
                     (hl ? srcAl : srcAh) + (u64)r * 512 + ch * 64 + q * 16);
            } else {
                int t = s - 512;
                int hl = t >> 10, u = t & 1023;
                int r = u >> 2, q = u & 3;
                CP16(dbase + 2 * PJ_A + hl * PJ_B + r * 80 + q * 16,
                     (hl ? srcBl : srcBh) + (u64)r * 512 + ch * 64 + q * 16);
            }
        }
        CP_COMMIT();
    };

    const int q = lane >> 3, r = lane & 7;
    const u32 aB = smb + (wn * 32 + (q & 1) * 8 + r) * 80 + (q >> 1) * 16;
    const u32 bB = smb + 2 * PJ_A + (wm * 32 + (q & 1) * 8 + r) * 80 + (q >> 1) * 16;

    float C[2][4][4];
    #pragma unroll
    for (int i = 0; i < 2; i++)
        #pragma unroll
        for (int j = 0; j < 4; j++)
            #pragma unroll
            for (int k = 0; k < 4; k++) C[i][j][k] = 0.f;

    load_chunk(0, 0);
    for (int ch = 0; ch < 8; ch++) {
        const int buf = ch & 1;
        if (ch < 7) { load_chunk(ch + 1, buf ^ 1); CP_WAIT(1); }
        else        { CP_WAIT(0); }
        __syncthreads();

        const u32 A0 = aB + buf * PJ_STG;
        const u32 B0 = bB + buf * PJ_STG;
        #pragma unroll
        for (int ks = 0; ks < 2; ks++) {
            u32 ah[2][4], al[2][4], bh[2][4], bl[2][4];
            #pragma unroll
            for (int ni = 0; ni < 2; ni++) {
                ldmx4(ah[ni], A0 + ks * 32 + ni * 16 * 80);
                ldmx4(al[ni], A0 + ks * 32 + ni * 16 * 80 + PJ_A);
            }
            #pragma unroll
            for (int p = 0; p < 2; p++) {
                ldmx4(bh[p], B0 + ks * 32 + p * 16 * 80);
                ldmx4(bl[p], B0 + ks * 32 + p * 16 * 80 + PJ_B);
            }
            #pragma unroll
            for (int ni = 0; ni < 2; ni++)
                #pragma unroll
                for (int mj = 0; mj < 4; mj++) {
                    const int p = mj >> 1, w = mj & 1;
                    mma_bf16(C[ni][mj], ah[ni], bh[p][w], bh[p][w + 2]);
                    mma_bf16(C[ni][mj], ah[ni], bl[p][w], bl[p][w + 2]);
                    mma_bf16(C[ni][mj], al[ni], bh[p][w], bh[p][w + 2]);
                }
        }
        __syncthreads();
    }

    // ---- epilogue: bias, norms, normalize, hi/lo store ----
    float sl[2] = {0.f, 0.f}, sh[2] = {0.f, 0.f};
    #pragma unroll
    for (int ni = 0; ni < 2; ni++)
        #pragma unroll
        for (int mj = 0; mj < 4; mj++) {
            float2 bb = *(const float2*)&g_bias[m0 + wm * 32 + mj * 8 + (lane & 3) * 2];
            C[ni][mj][0] += bb.x; C[ni][mj][1] += bb.y;
            C[ni][mj][2] += bb.x; C[ni][mj][3] += bb.y;
            sl[ni] += C[ni][mj][0]*C[ni][mj][0] + C[ni][mj][1]*C[ni][mj][1];
            sh[ni] += C[ni][mj][2]*C[ni][mj][2] + C[ni][mj][3]*C[ni][mj][3];
        }
    #pragma unroll
    for (int ni = 0; ni < 2; ni++) {
        sl[ni] += __shfl_xor_sync(0xFFFFFFFFu, sl[ni], 1);
        sl[ni] += __shfl_xor_sync(0xFFFFFFFFu, sl[ni], 2);
        sh[ni] += __shfl_xor_sync(0xFFFFFFFFu, sh[ni], 1);
        sh[ni] += __shfl_xor_sync(0xFFFFFFFFu, sh[ni], 2);
    }
    float* normsm = (float*)sm;          // [64][8]
    float* invsm  = normsm + 512;        // [64]
    if ((lane & 3) == 0) {
        int rl = wn * 32 + (lane >> 2);
        #pragma unroll
        for (int ni = 0; ni < 2; ni++) {
            normsm[(rl + ni * 16) * 8 + wm]     = sl[ni];
            normsm[(rl + ni * 16 + 8) * 8 + wm] = sh[ni];
        }
    }
    __syncthreads();
    if (tid < 64) {
        float s = 0.f;
        #pragma unroll
        for (int w = 0; w < 8; w++) s += normsm[tid * 8 + w];
        invsm[tid] = 1.0f / fmaxf(sqrtf(s), 1e-12f);
    }
    __syncthreads();

    __nv_bfloat16* Hh = mh ? g_qhi : g_khi;
    __nv_bfloat16* Hl = mh ? g_qlo : g_klo;
    const int cu = (wm * 32 + (lane & 3) * 2) >> 1;   // u32 col base
    #pragma unroll
    for (int ni = 0; ni < 2; ni++) {
        int rl = wn * 32 + ni * 16 + (lane >> 2);
        float il = invsm[rl], ih = invsm[rl + 8];
        u32* dh0 = (u32*)(Hh + (size_t)(b * HW_ + n0 + rl) * C_) + cu;
        u32* dl0 = (u32*)(Hl + (size_t)(b * HW_ + n0 + rl) * C_) + cu;
        u32* dh1 = (u32*)(Hh + (size_t)(b * HW_ + n0 + rl + 8) * C_) + cu;
        u32* dl1 = (u32*)(Hl + (size_t)(b * HW_ + n0 + rl + 8) * C_) + cu;
        #pragma unroll
        for (int mj = 0; mj < 4; mj++) {
            u32 hh, ll;
            split_pair(C[ni][mj][0] * il, C[ni][mj][1] * il, hh, ll);
            dh0[mj * 4] = hh; dl0[mj * 4] = ll;
            split_pair(C[ni][mj][2] * ih, C[ni][mj][3] * ih, hh, ll);
            dh1[mj * 4] = hh; dl1[mj * 4] = ll;
        }
    }
}

// ---------------------------------------------------------------------------
// Attention via mma.sync: block = 128n x 128m x K=256.
// ---------------------------------------------------------------------------
#define TILE_B  10240
#define BUF_B   (4 * TILE_B)
#define ATTN_SMEM (2 * BUF_B)

__global__ __launch_bounds__(256, 2) void attn_kernel()
{
    extern __shared__ __align__(16) char sm[];
    const u32 smb = smem_u32(sm);
    const int tid = threadIdx.x, lane = tid & 31, wid = tid >> 5;
    const int wn = wid >> 2, wm = wid & 3;
    const int m0 = blockIdx.x * 128, b = blockIdx.y, nz = blockIdx.z;
    const int n0 = nz * 128;

    const char* srcA[2] = { (const char*)(g_khi + (size_t)(b * HW_ + n0) * C_),
                            (const char*)(g_klo + (size_t)(b * HW_ + n0) * C_) };
    const char* srcB[2] = { (const char*)(g_qhi + (size_t)(b * HW_ + m0) * C_),
                            (const char*)(g_qlo + (size_t)(b * HW_ + m0) * C_) };

    auto load_chunk = [&](int ch, int buf) {
        const u32 dbase = smb + buf * BUF_B;
        #pragma unroll
        for (int it = 0; it < 2; it++) {
            int t = tid + 256 * it;
            int row = t >> 2, seg = t & 3;
            u32 doff = row * 80 + seg * 16;
            u64 soff = (u64)row * 512 + ch * 64 + seg * 16;
            CP16(dbase + 0 * TILE_B + doff, srcA[0] + soff);
            CP16(dbase + 1 * TILE_B + doff, srcA[1] + soff);
            CP16(dbase + 2 * TILE_B + doff, srcB[0] + soff);
            CP16(dbase + 3 * TILE_B + doff, srcB[1] + soff);
        }
        CP_COMMIT();
    };

    const int q = lane >> 3, r = lane & 7;
    const u32 aB = smb + (wn * 64 + (q & 1) * 8 + r) * 80 + (q >> 1) * 16;
    const u32 bB = smb + 2 * TILE_B + (wm * 32 + (q & 1) * 8 + r) * 80 + (q >> 1) * 16;

    float C[4][4][4];
    #pragma unroll
    for (int i = 0; i < 4; i++)
        #pragma unroll
        for (int j = 0; j < 4; j++)
            #pragma unroll
            for (int k = 0; k < 4; k++) C[i][j][k] = 0.f;

    float v0[4], v1[4];
    #pragma unroll
    for (int ni = 0; ni < 4; ni++) {
        int nr = n0 + wn * 64 + ni * 16 + (lane >> 2);
        v0[ni] = g_v[b * HW_ + nr];
        v1[ni] = g_v[b * HW_ + nr + 8];
    }

    load_chunk(0, 0);
    for (int ch = 0; ch < 8; ch++) {
        const int buf = ch & 1;
        if (ch < 7) { load_chunk(ch + 1, buf ^ 1); CP_WAIT(1); }
        else        { CP_WAIT(0); }
        __syncthreads();

        const u32 A0 = aB + buf * BUF_B;
        const u32 B0 = bB + buf * BUF_B;
        #pragma unroll
        for (int ks = 0; ks < 2; ks++) {
            u32 ah[4][4], al[4][4], bh[2][4], bl[2][4];
            #pragma unroll
            for (int ni = 0; ni < 4; ni++) {
                ldmx4(ah[ni], A0 + ks * 32 + ni * 16 * 80);
                ldmx4(al[ni], A0 + ks * 32 + ni * 16 * 80 + TILE_B);
            }
            #pragma unroll
            for (int p = 0; p < 2; p++) {
                ldmx4(bh[p], B0 + ks * 32 + p * 16 * 80);
                ldmx4(bl[p], B0 + ks * 32 + p * 16 * 80 + TILE_B);
            }
            #pragma unroll
            for (int ni = 0; ni < 4; ni++)
                #pragma unroll
                for (int mj = 0; mj < 4; mj++) {
                    const int p = mj >> 1, w = mj & 1;
                    mma_bf16(C[ni][mj], ah[ni], bh[p][w], bh[p][w + 2]);
                    mma_bf16(C[ni][mj], ah[ni], bl[p][w], bl[p][w + 2]);
                    mma_bf16(C[ni][mj], al[ni], bh[p][w], bh[p][w + 2]);
                }
        }
        __syncthreads();
    }

    float dsum[4][2] = {}, nsum[4][2] = {};
    #pragma unroll
    for (int ni = 0; ni < 4; ni++)
        #pragma unroll
        for (int mj = 0; mj < 4; mj++) {
            float e0 = exp_poly(C[ni][mj][0]);
            float e1 = exp_poly(C[ni][mj][1]);
            float e2 = exp_poly(C[ni][mj][2]);
            float e3 = exp_poly(C[ni][mj][3]);
            dsum[mj][0] += e0 + e2;
            dsum[mj][1] += e1 + e3;
            nsum[mj][0] = fmaf(v0[ni], e0, fmaf(v1[ni], e2, nsum[mj][0]));
            nsum[mj][1] = fmaf(v0[ni], e1, fmaf(v1[ni], e3, nsum[mj][1]));
        }
    #pragma unroll
    for (int mj = 0; mj < 4; mj++)
        #pragma unroll
        for (int h = 0; h < 2; h++) {
            #pragma unroll
            for (int msk = 4; msk <= 16; msk <<= 1) {
                dsum[mj][h] += __shfl_xor_sync(0xFFFFFFFFu, dsum[mj][h], msk);
                nsum[mj][h] += __shfl_xor_sync(0xFFFFFFFFu, nsum[mj][h], msk);
            }
        }

    float* redD = (float*)sm;
    float* redN = redD + 256;
    if (lane < 4) {
        #pragma unroll
        for (int mj = 0; mj < 4; mj++)
            #pragma unroll
            for (int h = 0; h < 2; h++) {
                int col = wm * 32 + mj * 8 + lane * 2 + h;
                redD[wn * 128 + col] = dsum[mj][h];
                redN[wn * 128 + col] = nsum[mj][h];
            }
    }
    __syncthreads();
    if (tid < 128) {
        g_pd[(size_t)(nz * B_ + b) * HW_ + m0 + tid] = redD[tid] + redD[128 + tid];
        g_pn[(size_t)(nz * B_ + b) * HW_ + m0 + tid] = redN[tid] + redN[128 + tid];
    }
}

// ---------------------------------------------------------------------------
// Combine partials: G = sum(num) / sum(den)
// ---------------------------------------------------------------------------
__global__ __launch_bounds__(256) void gfinal_kernel()
{
    int t = blockIdx.x * 256 + threadIdx.x;
    float D = 0.f, N = 0.f;
    #pragma unroll
    for (int z = 0; z < NSPLIT; z++) {
        D += g_pd[z * B_ * HW_ + t];
        N += g_pn[z * B_ * HW_ + t];
    }
    g_G[t] = N / D;
}

// ---------------------------------------------------------------------------
// Conv: out[b,c,i,j] = 3x3 box-sum of G[b,hw]*batch[b,c,hw]
// ---------------------------------------------------------------------------
__global__ __launch_bounds__(256) void conv_kernel(
    const float* __restrict__ batch, float* __restrict__ out)
{
    __shared__ float ys[HW_];
    const int c = blockIdx.x, b = blockIdx.y;
    const float* xb = batch + (b * C_ + c) * HW_;
    const float* Gb = g_G + b * HW_;
    for (int i = threadIdx.x; i < HW_; i += 256) ys[i] = Gb[i] * xb[i];
    __syncthreads();
    float* ob = out + (b * C_ + c) * 900;
    for (int o = threadIdx.x; o < 900; o += 256) {
        int i = o / 30, j = o - i * 30;
        const float* y = ys + i * 32 + j;
        ob[o] = y[0] + y[1] + y[2] +
                y[32] + y[33] + y[34] +
                y[64] + y[65] + y[66];
    }
}

extern "C" void kernel_launch(void* const* d_in, const int* in_sizes, int n_in,
                              void* d_out, int out_size)
{
    const float* batch   = (const float*)d_in[0];
    const float* key_w   = (const float*)d_in[1];
    const float* key_b   = (const float*)d_in[2];
    const float* query_w = (const float*)d_in[3];
    const float* query_b = (const float*)d_in[4];
    const float* value_w = (const float*)d_in[5];
    const float* value_b = (const float*)d_in[6];
    // d_in[7] = local_indices (unused: collapses analytically to 3x3 box filter)

    cudaFuncSetAttribute(proj_kernel, cudaFuncAttributeMaxDynamicSharedMemorySize, PROJ_SMEM);
    cudaFuncSetAttribute(attn_kernel, cudaFuncAttributeMaxDynamicSharedMemorySize, ATTN_SMEM);

    setup_kernel<<<512, 256>>>(key_w, query_w, key_b, query_b);
    xsplit_kernel<<<dim3(32, 16), 256>>>(batch, value_w, value_b);
    proj_kernel<<<dim3(16, 16, 2), 512, PROJ_SMEM>>>();
    attn_kernel<<<dim3(8, 16, NSPLIT), 256, ATTN_SMEM>>>();
    gfinal_kernel<<<64, 256>>>();
    conv_kernel<<<dim3(256, 16), 256>>>(batch, (float*)d_out);
}

// round 8
// speedup vs baseline: 6.6131x; 2.0087x over previous
#include <cuda_runtime.h>
#include <cuda_fp16.h>

#define B_  16
#define C_  256
#define HW_ 1024
#define NSPLIT 8

// ---- device scratch (no allocations allowed) ----
__device__ __half g_xh[B_ * HW_ * C_];   // x transposed [b][n][c], fp16
__device__ __half g_wh[512 * C_];        // weights [m][k]: m<256 K, else Q
__device__ __half g_kh[B_ * HW_ * C_];   // normalized keys    [b][n][c]
__device__ __half g_qh[B_ * HW_ * C_];   // normalized queries [b][m][c]
__device__ float g_bias[512];
__device__ float g_v[B_ * HW_];            // value scalars
__device__ float g_G[B_ * HW_];            // softmax aggregate
__device__ float g_pd[NSPLIT * B_ * HW_];  // partial denominators
__device__ float g_pn[NSPLIT * B_ * HW_];  // partial numerators

typedef unsigned int       u32;
typedef unsigned long long u64;

__device__ __forceinline__ u32 smem_u32(const void* p) {
    u32 a; asm("{ .reg .u64 t; cvta.to.shared.u64 t,%1; cvt.u32.u64 %0,t; }" : "=r"(a) : "l"(p));
    return a;
}
__device__ __forceinline__ void ldmx4(u32* r, u32 addr) {
    asm volatile("ldmatrix.sync.aligned.m8n8.x4.shared.b16 {%0,%1,%2,%3},[%4];"
                 : "=r"(r[0]), "=r"(r[1]), "=r"(r[2]), "=r"(r[3]) : "r"(addr));
}
__device__ __forceinline__ void mma_f16(float* c, const u32* a, u32 b0, u32 b1) {
    asm volatile("mma.sync.aligned.m16n8k16.row.col.f32.f16.f16.f32 "
                 "{%0,%1,%2,%3},{%4,%5,%6,%7},{%8,%9},{%0,%1,%2,%3};"
                 : "+f"(c[0]), "+f"(c[1]), "+f"(c[2]), "+f"(c[3])
                 : "r"(a[0]), "r"(a[1]), "r"(a[2]), "r"(a[3]), "r"(b0), "r"(b1));
}
#define CP16(sa, ga) asm volatile("cp.async.cg.shared.global [%0],[%1],16;" :: "r"(sa), "l"(ga))
#define CP_COMMIT()  asm volatile("cp.async.commit_group;" ::: "memory")
#define CP_WAIT(N)   asm volatile("cp.async.wait_group %0;" :: "n"(N) : "memory")

__device__ __forceinline__ u32 pack_h2(float a, float b) {
    __half2 t = __floats2half2_rn(a, b);
    return *(u32*)&t;
}

// exp(s) for s in [-1,1]: degree-8 Taylor (max rel err ~7.5e-6), FMA pipe only.
__device__ __forceinline__ float exp_poly(float s) {
    float e = fmaf(2.4801587e-5f, s, 1.9841270e-4f);
    e = fmaf(e, s, 1.3888889e-3f);
    e = fmaf(e, s, 8.3333333e-3f);
    e = fmaf(e, s, 4.1666667e-2f);
    e = fmaf(e, s, 0.16666667f);
    e = fmaf(e, s, 0.5f);
    e = fmaf(e, s, 1.0f);
    e = fmaf(e, s, 1.0f);
    return e;
}

// ---------------------------------------------------------------------------
// Setup: weights fp16 [m][k] (m 0..511: K then Q), biases fp32.
// ---------------------------------------------------------------------------
__global__ __launch_bounds__(256) void setup_kernel(
    const float* __restrict__ kw, const float* __restrict__ qw,
    const float* __restrict__ kb, const float* __restrict__ qb)
{
    int idx = blockIdx.x * 256 + threadIdx.x;      // 512x256 = 131072
    if (idx < 512) g_bias[idx] = (idx < 256) ? kb[idx] : qb[idx - 256];
    int m = idx >> 8, k = idx & 255;
    float w = (m < 256) ? kw[m * C_ + k] : qw[(m - 256) * C_ + k];
    g_wh[idx] = __float2half(w);
}

// ---------------------------------------------------------------------------
// xsplit: transpose batch [b][c][n] -> fp16 [b][n][c], fold value GEMV.
// ---------------------------------------------------------------------------
__global__ __launch_bounds__(256) void xsplit_kernel(
    const float* __restrict__ batch, const float* __restrict__ vw,
    const float* __restrict__ vb)
{
    __shared__ float xs[32 * 264 + 8];   // addr = j*264 + c + (c>>5)
    __shared__ float wsm[256];
    __shared__ float vp[256];
    const int b = blockIdx.y, n0 = blockIdx.x * 32;
    const int tid = threadIdx.x;
    wsm[tid] = vw[tid];

    #pragma unroll
    for (int it = 0; it < 32; it++) {
        int idx = it * 256 + tid;
        int c = idx >> 5, j = idx & 31;
        xs[j * 264 + c + (c >> 5)] = batch[(b * C_ + c) * HW_ + n0 + j];
    }
    __syncthreads();

    // value partials: warp w sums c in [32w, 32w+32) for position j
    {
        const int w = tid >> 5, j = tid & 31;
        float p = 0.f;
        #pragma unroll
        for (int cc = 0; cc < 32; cc++) {
            int c = w * 32 + cc;
            p = fmaf(xs[j * 264 + c + (c >> 5)], wsm[c], p);
        }
        vp[w * 32 + j] = p;
    }
    __syncthreads();
    if (tid < 32) {
        float s = vb[0];
        #pragma unroll
        for (int w = 0; w < 8; w++) s += vp[w * 32 + tid];
        g_v[b * HW_ + n0 + tid] = s;
    }

    // transpose write: thread = (n' = tid>>3, seg = tid&7), 32 c's per seg
    const int np = tid >> 3, seg = tid & 7, c0 = seg * 32;
    u32 h[16];
    #pragma unroll
    for (int i = 0; i < 16; i++) {
        int c = c0 + 2 * i;
        float a = xs[np * 264 + c + (c >> 5)];
        float d = xs[np * 264 + c + 1 + ((c + 1) >> 5)];
        h[i] = pack_h2(a, d);
    }
    u32* dh = (u32*)(g_xh + (size_t)(b * HW_ + n0 + np) * C_) + seg * 16;
    #pragma unroll
    for (int k = 0; k < 4; k++)
        *(uint4*)(dh + 4 * k) = make_uint4(h[4*k], h[4*k+1], h[4*k+2], h[4*k+3]);
}

// ---------------------------------------------------------------------------
// Proj via fp16 mma.sync (single product): block = 64n x 256m x K=256.
// grid (16 ntile, 16 b, 2 mh), 512 threads (16 warps = 2n x 8m, warp 32x32).
// Depth-3 cp.async pipeline. Epilogue: +bias, row norms, fp16 store.
// smem/stage: A[64x80B]=5120 + B[256x80B]=20480 -> 25600, x3 = 76800.
// ---------------------------------------------------------------------------
#define PJ_A    5120
#define PJ_STG  25600
#define PROJ_SMEM (3 * PJ_STG)

__global__ __launch_bounds__(512, 1) void proj_kernel()
{
    extern __shared__ __align__(16) char sm[];
    const u32 smb = smem_u32(sm);
    const int tid = threadIdx.x, lane = tid & 31, wid = tid >> 5;
    const int wn = wid >> 3, wm = wid & 7;
    const int n0 = blockIdx.x * 64;
    const int b  = blockIdx.y;
    const int mh = blockIdx.z;
    const int m0 = mh * 256;

    const char* srcA = (const char*)(g_xh + (size_t)(b * HW_ + n0) * C_);
    const char* srcB = (const char*)(g_wh + (size_t)m0 * C_);

    auto load_chunk = [&](int ch, int buf) {
        const u32 dbase = smb + buf * PJ_STG;
        #pragma unroll
        for (int it = 0; it < 3; it++) {
            int s = it * 512 + tid;
            if (s < 256) {
                int r = s >> 2, q = s & 3;
                CP16(dbase + r * 80 + q * 16, srcA + (u64)r * 512 + ch * 64 + q * 16);
            } else if (s < 1280) {
                int u = s - 256;
                int r = u >> 2, q = u & 3;
                CP16(dbase + PJ_A + r * 80 + q * 16, srcB + (u64)r * 512 + ch * 64 + q * 16);
            }
        }
        CP_COMMIT();
    };

    const int q = lane >> 3, r = lane & 7;
    const u32 aB = smb + (wn * 32 + (q & 1) * 8 + r) * 80 + (q >> 1) * 16;
    const u32 bB = smb + PJ_A + (wm * 32 + (q & 1) * 8 + r) * 80 + (q >> 1) * 16;

    float C[2][4][4];
    #pragma unroll
    for (int i = 0; i < 2; i++)
        #pragma unroll
        for (int j = 0; j < 4; j++)
            #pragma unroll
            for (int k = 0; k < 4; k++) C[i][j][k] = 0.f;

    load_chunk(0, 0);
    load_chunk(1, 1);
    for (int ch = 0; ch < 8; ch++) {
        if (ch < 6) CP_WAIT(1); else if (ch == 6) CP_WAIT(1); else CP_WAIT(0);
        __syncthreads();
        if (ch < 6) load_chunk(ch + 2, (ch + 2) % 3);

        const int buf = ch % 3;
        const u32 A0 = aB + buf * PJ_STG;
        const u32 B0 = bB + buf * PJ_STG;
        #pragma unroll
        for (int ks = 0; ks < 2; ks++) {
            u32 ah[2][4], bh[2][4];
            #pragma unroll
            for (int ni = 0; ni < 2; ni++)
                ldmx4(ah[ni], A0 + ks * 32 + ni * 16 * 80);
            #pragma unroll
            for (int p = 0; p < 2; p++)
                ldmx4(bh[p], B0 + ks * 32 + p * 16 * 80);
            #pragma unroll
            for (int ni = 0; ni < 2; ni++)
                #pragma unroll
                for (int mj = 0; mj < 4; mj++) {
                    const int p = mj >> 1, w = mj & 1;
                    mma_f16(C[ni][mj], ah[ni], bh[p][w], bh[p][w + 2]);
                }
        }
    }
    __syncthreads();

    // ---- epilogue: bias, norms, normalize, fp16 store ----
    float sl[2] = {0.f, 0.f}, sh[2] = {0.f, 0.f};
    #pragma unroll
    for (int ni = 0; ni < 2; ni++)
        #pragma unroll
        for (int mj = 0; mj < 4; mj++) {
            float2 bb = *(const float2*)&g_bias[m0 + wm * 32 + mj * 8 + (lane & 3) * 2];
            C[ni][mj][0] += bb.x; C[ni][mj][1] += bb.y;
            C[ni][mj][2] += bb.x; C[ni][mj][3] += bb.y;
            sl[ni] += C[ni][mj][0]*C[ni][mj][0] + C[ni][mj][1]*C[ni][mj][1];
            sh[ni] += C[ni][mj][2]*C[ni][mj][2] + C[ni][mj][3]*C[ni][mj][3];
        }
    #pragma unroll
    for (int ni = 0; ni < 2; ni++) {
        sl[ni] += __shfl_xor_sync(0xFFFFFFFFu, sl[ni], 1);
        sl[ni] += __shfl_xor_sync(0xFFFFFFFFu, sl[ni], 2);
        sh[ni] += __shfl_xor_sync(0xFFFFFFFFu, sh[ni], 1);
        sh[ni] += __shfl_xor_sync(0xFFFFFFFFu, sh[ni], 2);
    }
    float* normsm = (float*)sm;          // [64][8]
    float* invsm  = normsm + 512;        // [64]
    if ((lane & 3) == 0) {
        int rl = wn * 32 + (lane >> 2);
        #pragma unroll
        for (int ni = 0; ni < 2; ni++) {
            normsm[(rl + ni * 16) * 8 + wm]     = sl[ni];
            normsm[(rl + ni * 16 + 8) * 8 + wm] = sh[ni];
        }
    }
    __syncthreads();
    if (tid < 64) {
        float s = 0.f;
        #pragma unroll
        for (int w = 0; w < 8; w++) s += normsm[tid * 8 + w];
        invsm[tid] = 1.0f / fmaxf(sqrtf(s), 1e-12f);
    }
    __syncthreads();

    __half* H = mh ? g_qh : g_kh;
    const int cu = (wm * 32 + (lane & 3) * 2) >> 1;   // u32 col base
    #pragma unroll
    for (int ni = 0; ni < 2; ni++) {
        int rl = wn * 32 + ni * 16 + (lane >> 2);
        float il = invsm[rl], ih = invsm[rl + 8];
        u32* d0 = (u32*)(H + (size_t)(b * HW_ + n0 + rl) * C_) + cu;
        u32* d1 = (u32*)(H + (size_t)(b * HW_ + n0 + rl + 8) * C_) + cu;
        #pragma unroll
        for (int mj = 0; mj < 4; mj++) {
            d0[mj * 4] = pack_h2(C[ni][mj][0] * il, C[ni][mj][1] * il);
            d1[mj * 4] = pack_h2(C[ni][mj][2] * ih, C[ni][mj][3] * ih);
        }
    }
}

// ---------------------------------------------------------------------------
// Attention via fp16 mma.sync (single product): block = 128n x 128m x K=256.
// grid (8 m, 16 b, 8 nsplit), 256 threads (8 warps = 2n x 4m, warp 64x32).
// Depth-3 cp.async pipeline. Epilogue: poly exp + column reduce -> partials.
// smem/stage: A[128x80B] + B[128x80B] = 20480, x3 = 61440.
// ---------------------------------------------------------------------------
#define AT_TILE 10240
#define AT_STG  20480
#define ATTN_SMEM (3 * AT_STG)

__global__ __launch_bounds__(256, 2) void attn_kernel()
{
    extern __shared__ __align__(16) char sm[];
    const u32 smb = smem_u32(sm);
    const int tid = threadIdx.x, lane = tid & 31, wid = tid >> 5;
    const int wn = wid >> 2, wm = wid & 3;
    const int m0 = blockIdx.x * 128, b = blockIdx.y, nz = blockIdx.z;
    const int n0 = nz * 128;

    const char* srcA = (const char*)(g_kh + (size_t)(b * HW_ + n0) * C_);
    const char* srcB = (const char*)(g_qh + (size_t)(b * HW_ + m0) * C_);

    auto load_chunk = [&](int ch, int buf) {
        const u32 dbase = smb + buf * AT_STG;
        #pragma unroll
        for (int it = 0; it < 4; it++) {
            int s = it * 256 + tid;
            if (s < 512) {
                int r = s >> 2, q = s & 3;
                CP16(dbase + r * 80 + q * 16, srcA + (u64)r * 512 + ch * 64 + q * 16);
            } else {
                int u = s - 512;
                int r = u >> 2, q = u & 3;
                CP16(dbase + AT_TILE + r * 80 + q * 16, srcB + (u64)r * 512 + ch * 64 + q * 16);
            }
        }
        CP_COMMIT();
    };

    const int q = lane >> 3, r = lane & 7;
    const u32 aB = smb + (wn * 64 + (q & 1) * 8 + r) * 80 + (q >> 1) * 16;
    const u32 bB = smb + AT_TILE + (wm * 32 + (q & 1) * 8 + r) * 80 + (q >> 1) * 16;

    float C[4][4][4];
    #pragma unroll
    for (int i = 0; i < 4; i++)
        #pragma unroll
        for (int j = 0; j < 4; j++)
            #pragma unroll
            for (int k = 0; k < 4; k++) C[i][j][k] = 0.f;

    float v0[4], v1[4];
    #pragma unroll
    for (int ni = 0; ni < 4; ni++) {
        int nr = n0 + wn * 64 + ni * 16 + (lane >> 2);
        v0[ni] = g_v[b * HW_ + nr];
        v1[ni] = g_v[b * HW_ + nr + 8];
    }

    load_chunk(0, 0);
    load_chunk(1, 1);
    for (int ch = 0; ch < 8; ch++) {
        if (ch < 7) CP_WAIT(1); else CP_WAIT(0);
        __syncthreads();
        if (ch < 6) load_chunk(ch + 2, (ch + 2) % 3);

        const int buf = ch % 3;
        const u32 A0 = aB + buf * AT_STG;
        const u32 B0 = bB + buf * AT_STG;
        #pragma unroll
        for (int ks = 0; ks < 2; ks++) {
            u32 ah[4][4], bh[2][4];
            #pragma unroll
            for (int ni = 0; ni < 4; ni++)
                ldmx4(ah[ni], A0 + ks * 32 + ni * 16 * 80);
            #pragma unroll
            for (int p = 0; p < 2; p++)
                ldmx4(bh[p], B0 + ks * 32 + p * 16 * 80);
            #pragma unroll
            for (int ni = 0; ni < 4; ni++)
                #pragma unroll
                for (int mj = 0; mj < 4; mj++) {
                    const int p = mj >> 1, w = mj & 1;
                    mma_f16(C[ni][mj], ah[ni], bh[p][w], bh[p][w + 2]);
                }
        }
    }

    float dsum[4][2] = {}, nsum[4][2] = {};
    #pragma unroll
    for (int ni = 0; ni < 4; ni++)
        #pragma unroll
        for (int mj = 0; mj < 4; mj++) {
            float e0 = exp_poly(C[ni][mj][0]);
            float e1 = exp_poly(C[ni][mj][1]);
            float e2 = exp_poly(C[ni][mj][2]);
            float e3 = exp_poly(C[ni][mj][3]);
            dsum[mj][0] += e0 + e2;
            dsum[mj][1] += e1 + e3;
            nsum[mj][0] = fmaf(v0[ni], e0, fmaf(v1[ni], e2, nsum[mj][0]));
            nsum[mj][1] = fmaf(v0[ni], e1, fmaf(v1[ni], e3, nsum[mj][1]));
        }
    #pragma unroll
    for (int mj = 0; mj < 4; mj++)
        #pragma unroll
        for (int h = 0; h < 2; h++) {
            #pragma unroll
            for (int msk = 4; msk <= 16; msk <<= 1) {
                dsum[mj][h] += __shfl_xor_sync(0xFFFFFFFFu, dsum[mj][h], msk);
                nsum[mj][h] += __shfl_xor_sync(0xFFFFFFFFu, nsum[mj][h], msk);
            }
        }

    __syncthreads();
    float* redD = (float*)sm;
    float* redN = redD + 256;
    if (lane < 4) {
        #pragma unroll
        for (int mj = 0; mj < 4; mj++)
            #pragma unroll
            for (int h = 0; h < 2; h++) {
                int col = wm * 32 + mj * 8 + lane * 2 + h;
                redD[wn * 128 + col] = dsum[mj][h];
                redN[wn * 128 + col] = nsum[mj][h];
            }
    }
    __syncthreads();
    if (tid < 128) {
        g_pd[(size_t)(nz * B_ + b) * HW_ + m0 + tid] = redD[tid] + redD[128 + tid];
        g_pn[(size_t)(nz * B_ + b) * HW_ + m0 + tid] = redN[tid] + redN[128 + tid];
    }
}

// ---------------------------------------------------------------------------
// Combine partials: G = sum(num) / sum(den)
// ---------------------------------------------------------------------------
__global__ __launch_bounds__(256) void gfinal_kernel()
{
    int t = blockIdx.x * 256 + threadIdx.x;
    float D = 0.f, N = 0.f;
    #pragma unroll
    for (int z = 0; z < NSPLIT; z++) {
        D += g_pd[z * B_ * HW_ + t];
        N += g_pn[z * B_ * HW_ + t];
    }
    g_G[t] = N / D;
}

// ---------------------------------------------------------------------------
// Conv: out[b,c,i,j] = 3x3 box-sum of G[b,hw]*batch[b,c,hw]
// ---------------------------------------------------------------------------
__global__ __launch_bounds__(256) void conv_kernel(
    const float* __restrict__ batch, float* __restrict__ out)
{
    __shared__ float ys[HW_];
    const int c = blockIdx.x, b = blockIdx.y;
    const float* xb = batch + (b * C_ + c) * HW_;
    const float* Gb = g_G + b * HW_;
    for (int i = threadIdx.x; i < HW_; i += 256) ys[i] = Gb[i] * xb[i];
    __syncthreads();
    float* ob = out + (b * C_ + c) * 900;
    for (int o = threadIdx.x; o < 900; o += 256) {
        int i = o / 30, j = o - i * 30;
        const float* y = ys + i * 32 + j;
        ob[o] = y[0] + y[1] + y[2] +
                y[32] + y[33] + y[34] +
                y[64] + y[65] + y[66];
    }
}

extern "C" void kernel_launch(void* const* d_in, const int* in_sizes, int n_in,
                              void* d_out, int out_size)
{
    const float* batch   = (const float*)d_in[0];
    const float* key_w   = (const float*)d_in[1];
    const float* key_b   = (const float*)d_in[2];
    const float* query_w = (const float*)d_in[3];
    const float* query_b = (const float*)d_in[4];
    const float* value_w = (const float*)d_in[5];
    const float* value_b = (const float*)d_in[6];
    // d_in[7] = local_indices (unused: collapses analytically to 3x3 box filter)

    cudaFuncSetAttribute(proj_kernel, cudaFuncAttributeMaxDynamicSharedMemorySize, PROJ_SMEM);
    cudaFuncSetAttribute(attn_kernel, cudaFuncAttributeMaxDynamicSharedMemorySize, ATTN_SMEM);

    setup_kernel<<<512, 256>>>(key_w, query_w, key_b, query_b);
    xsplit_kernel<<<dim3(32, 16), 256>>>(batch, value_w, value_b);
    proj_kernel<<<dim3(16, 16, 2), 512, PROJ_SMEM>>>();
    attn_kernel<<<dim3(8, 16, NSPLIT), 256, ATTN_SMEM>>>();
    gfinal_kernel<<<64, 256>>>();
    conv_kernel<<<dim3(256, 16), 256>>>(batch, (float*)d_out);
}

// round 11
// speedup vs baseline: 7.8351x; 1.1848x over previous
#include <cuda_runtime.h>
#include <cuda_fp16.h>

#define B_  16
#define C_  256
#define HW_ 1024
#define NSPLIT 8

// ---- device scratch (no allocations allowed) ----
__device__ __half g_wh[512 * C_];        // weights [m][k]: m<256 K, else Q
__device__ __half g_kh[B_ * HW_ * C_];   // normalized keys    [b][n][c]
__device__ __half g_qh[B_ * HW_ * C_];   // normalized queries [b][m][c]
__device__ float g_bias[512];
__device__ float g_v[B_ * HW_];            // value scalars
__device__ float g_G[B_ * HW_];            // softmax aggregate
__device__ float g_pd[NSPLIT * B_ * HW_];  // partial denominators
__device__ float g_pn[NSPLIT * B_ * HW_];  // partial numerators

typedef unsigned int       u32;
typedef unsigned long long u64;

__device__ __forceinline__ u32 smem_u32(const void* p) {
    u32 a; asm("{ .reg .u64 t; cvta.to.shared.u64 t,%1; cvt.u32.u64 %0,t; }" : "=r"(a) : "l"(p));
    return a;
}
__device__ __forceinline__ void ldmx4(u32* r, u32 addr) {
    asm volatile("ldmatrix.sync.aligned.m8n8.x4.shared.b16 {%0,%1,%2,%3},[%4];"
                 : "=r"(r[0]), "=r"(r[1]), "=r"(r[2]), "=r"(r[3]) : "r"(addr));
}
__device__ __forceinline__ void mma_f16(float* c, const u32* a, u32 b0, u32 b1) {
    asm volatile("mma.sync.aligned.m16n8k16.row.col.f32.f16.f16.f32 "
                 "{%0,%1,%2,%3},{%4,%5,%6,%7},{%8,%9},{%0,%1,%2,%3};"
                 : "+f"(c[0]), "+f"(c[1]), "+f"(c[2]), "+f"(c[3])
                 : "r"(a[0]), "r"(a[1]), "r"(a[2]), "r"(a[3]), "r"(b0), "r"(b1));
}
#define CP16(sa, ga) asm volatile("cp.async.cg.shared.global [%0],[%1],16;" :: "r"(sa), "l"(ga))
#define CP_COMMIT()  asm volatile("cp.async.commit_group;" ::: "memory")
#define CP_WAIT(N)   asm volatile("cp.async.wait_group %0;" :: "n"(N) : "memory")

__device__ __forceinline__ u32 pack_h2(float a, float b) {
    __half2 t = __floats2half2_rn(a, b);
    return *(u32*)&t;
}

// exp(s) for s in [-1,1]: degree-8 Taylor (max rel err ~7.5e-6), FMA pipe only.
__device__ __forceinline__ float exp_poly(float s) {
    float e = fmaf(2.4801587e-5f, s, 1.9841270e-4f);
    e = fmaf(e, s, 1.3888889e-3f);
    e = fmaf(e, s, 8.3333333e-3f);
    e = fmaf(e, s, 4.1666667e-2f);
    e = fmaf(e, s, 0.16666667f);
    e = fmaf(e, s, 0.5f);
    e = fmaf(e, s, 1.0f);
    e = fmaf(e, s, 1.0f);
    return e;
}

// ---------------------------------------------------------------------------
// Setup: weights fp16 [m][k] (m 0..511: K then Q), biases fp32.
// ---------------------------------------------------------------------------
__global__ __launch_bounds__(256) void setup_kernel(
    const float* __restrict__ kw, const float* __restrict__ qw,
    const float* __restrict__ kb, const float* __restrict__ qb)
{
    int idx = blockIdx.x * 256 + threadIdx.x;      // 512x256 = 131072
    if (idx < 512) g_bias[idx] = (idx < 256) ? kb[idx] : qb[idx - 256];
    int m = idx >> 8, k = idx & 255;
    float w = (m < 256) ? kw[m * C_ + k] : qw[(m - 256) * C_ + k];
    g_wh[idx] = __float2half(w);
}

// ---------------------------------------------------------------------------
// Proj (fused): reads batch fp32, in-smem transpose -> fp16 A [n][c], value
// GEMV, then 64n x 512m x 256k fp16 GEMM (K cols 0..255, Q cols 256..511).
// 512 threads, 16 warps (2 wn x 8 wm), warp tile 32n x 64m.
// B (weights) triple-buffered in 32-col chunks; buf2 aliases dead fp32 stage.
// Mainloop ordering is WAIT -> sync -> issue (correct cp.async visibility).
// Epilogue: +bias, per-half row norms, normalized fp16 stores to g_kh/g_qh.
// ---------------------------------------------------------------------------
#define PA16_ST   528                       // A16 row stride bytes (64 rows)
#define PAS32_OFF 33792                     // fp32 staging, 256*65*4 = 66560 B
#define PAS32_F   8448                      // float index of staging
#define PB_TILE   40960                     // 512 rows x 80 B
#define PB01_OFF  100352                    // bufs 0,1
#define PSCR_F    45568                     // scratch float index (182272 B)
#define PROJ_SMEM 184832

__global__ __launch_bounds__(512, 1) void proj_kernel(
    const float* __restrict__ batch, const float* __restrict__ vw,
    const float* __restrict__ vb)
{
    extern __shared__ __align__(16) char sm[];
    float* smf = (float*)sm;
    const u32 smb = smem_u32(sm);
    const int tid = threadIdx.x, lane = tid & 31, wid = tid >> 5;
    const int wn = wid >> 3, wm = wid & 7;
    const int n0 = blockIdx.x * 64;
    const int b  = blockIdx.y;

    const char* srcB = (const char*)g_wh;

    // --- B prologue: chunks 0,1 into bufs 0,1 (cp.async; doesn't touch staging)
    {
        #pragma unroll
        for (int pc = 0; pc < 2; pc++) {
            const u32 dbase = smb + PB01_OFF + pc * PB_TILE;
            #pragma unroll
            for (int it = 0; it < 4; it++) {
                int s = tid + 512 * it;              // 2048 segs
                int r = s >> 2, q = s & 3;
                CP16(dbase + r * 80 + q * 16, srcB + (u64)r * 512 + pc * 64 + q * 16);
            }
            CP_COMMIT();
        }
    }

    // --- pass1: batch [c][n] fp32 -> staging smf[c*65 + n]
    #pragma unroll
    for (int it = 0; it < 8; it++) {
        int s = tid + 512 * it;                      // 4096 float4
        int c = s >> 4, nq = s & 15;
        float4 v4 = *(const float4*)(batch + ((size_t)(b * C_ + c)) * HW_ + n0 + 4 * nq);
        float* dst = smf + PAS32_F + c * 65 + 4 * nq;
        dst[0] = v4.x; dst[1] = v4.y; dst[2] = v4.z; dst[3] = v4.w;
    }
    __syncthreads();

    // --- pass2: staging -> A16 fp16 [n][c] (stride 528 B); 8192 half2 pairs
    #pragma unroll
    for (int it = 0; it < 16; it++) {
        int s = tid + 512 * it;                      // 64 rows x 128 pairs
        int cp = s & 127, n = s >> 7;
        float a = smf[PAS32_F + (2 * cp) * 65 + n];
        float d = smf[PAS32_F + (2 * cp + 1) * 65 + n];
        *(u32*)(sm + n * PA16_ST + 4 * cp) = pack_h2(a, d);
    }

    // --- value GEMV: warp w handles rows 4w..4w+3
    {
        const float vbv = __ldg(vb);
        #pragma unroll
        for (int rr = 0; rr < 4; rr++) {
            int n = 4 * wid + rr;
            float p = 0.f;
            #pragma unroll
            for (int j = 0; j < 8; j++) {
                int c = lane + 32 * j;
                p = fmaf(smf[PAS32_F + c * 65 + n], __ldg(vw + c), p);
            }
            #pragma unroll
            for (int o = 16; o; o >>= 1) p += __shfl_down_sync(0xFFFFFFFFu, p, o);
            if (lane == 0) g_v[b * HW_ + n0 + n] = p + vbv;
        }
    }
    __syncthreads();    // A16 ready; staging dead -> buf2 may alias it

    // --- ldmatrix lane bases
    const int qq = lane >> 3, rr = lane & 7;
    const u32 aBs = smb + (wn * 32 + (qq & 1) * 8 + rr) * PA16_ST + (qq >> 1) * 16;
    const u32 bLane = (wm * 64 + (qq & 1) * 8 + rr) * 80 + (qq >> 1) * 16;

    float C[2][8][4];
    #pragma unroll
    for (int i = 0; i < 2; i++)
        #pragma unroll
        for (int j = 0; j < 8; j++)
            #pragma unroll
            for (int k = 0; k < 4; k++) C[i][j][k] = 0.f;

    // --- mainloop: 8 chunks of 32 k-cols, depth-3 (buf2 aliased at PAS32_OFF)
    #pragma unroll
    for (int ch = 0; ch < 8; ch++) {
        if (ch < 7) { CP_WAIT(1); } else { CP_WAIT(0); }
        __syncthreads();
        if (ch < 6) {
            const int nb = (ch + 2) % 3;
            const u32 dbase = smb + (nb == 2 ? PAS32_OFF : PB01_OFF + nb * PB_TILE);
            #pragma unroll
            for (int it = 0; it < 4; it++) {
                int s = tid + 512 * it;
                int r = s >> 2, q = s & 3;
                CP16(dbase + r * 80 + q * 16, srcB + (u64)r * 512 + (ch + 2) * 64 + q * 16);
            }
            CP_COMMIT();
        }
        const int cb = ch % 3;
        const u32 B0 = smb + (cb == 2 ? PAS32_OFF : PB01_OFF + cb * PB_TILE) + bLane;
        const u32 A0 = aBs + ch * 64;
        #pragma unroll
        for (int ks = 0; ks < 2; ks++) {
            u32 ah[2][4], bh[4][4];
            #pragma unroll
            for (int ni = 0; ni < 2; ni++)
                ldmx4(ah[ni], A0 + ks * 32 + ni * 16 * PA16_ST);
            #pragma unroll
            for (int p = 0; p < 4; p++)
                ldmx4(bh[p], B0 + ks * 32 + p * 16 * 80);
            #pragma unroll
            for (int ni = 0; ni < 2; ni++)
                #pragma unroll
                for (int mj = 0; mj < 8; mj++) {
                    const int p = mj >> 1, w = mj & 1;
                    mma_f16(C[ni][mj], ah[ni], bh[p][w], bh[p][w + 2]);
                }
        }
    }
    __syncthreads();

    // --- epilogue: bias, per-half row norms, normalize, fp16 store ---
    float sl[2] = {0.f, 0.f}, sh[2] = {0.f, 0.f};
    #pragma unroll
    for (int ni = 0; ni < 2; ni++)
        #pragma unroll
        for (int mj = 0; mj < 8; mj++) {
            float2 bb = *(const float2*)&g_bias[wm * 64 + mj * 8 + (lane & 3) * 2];
            C[ni][mj][0] += bb.x; C[ni][mj][1] += bb.y;
            C[ni][mj][2] += bb.x; C[ni][mj][3] += bb.y;
            sl[ni] += C[ni][mj][0]*C[ni][mj][0] + C[ni][mj][1]*C[ni][mj][1];
            sh[ni] += C[ni][mj][2]*C[ni][mj][2] + C[ni][mj][3]*C[ni][mj][3];
        }
    #pragma unroll
    for (int ni = 0; ni < 2; ni++) {
        sl[ni] += __shfl_xor_sync(0xFFFFFFFFu, sl[ni], 1);
        sl[ni] += __shfl_xor_sync(0xFFFFFFFFu, sl[ni], 2);
        sh[ni] += __shfl_xor_sync(0xFFFFFFFFu, sh[ni], 1);
        sh[ni] += __shfl_xor_sync(0xFFFFFFFFu, sh[ni], 2);
    }
    float* normsm = smf + PSCR_F;        // [64 rows][8 wm]
    float* invsm  = normsm + 512;        // [64 rows][2 halves]
    if ((lane & 3) == 0) {
        int rbase = wn * 32 + (lane >> 2);
        #pragma unroll
        for (int ni = 0; ni < 2; ni++) {
            normsm[(rbase + ni * 16) * 8 + wm]     = sl[ni];
            normsm[(rbase + ni * 16 + 8) * 8 + wm] = sh[ni];
        }
    }
    __syncthreads();
    if (tid < 64) {
        float sK = 0.f, sQ = 0.f;
        #pragma unroll
        for (int w = 0; w < 4; w++) { sK += normsm[tid * 8 + w]; sQ += normsm[tid * 8 + 4 + w]; }
        invsm[tid * 2]     = 1.0f / fmaxf(sqrtf(sK), 1e-12f);
        invsm[tid * 2 + 1] = 1.0f / fmaxf(sqrtf(sQ), 1e-12f);
    }
    __syncthreads();

    __half* H = (wm < 4) ? g_kh : g_qh;
    const int half = (wm < 4) ? 0 : 1;
    const int cu = (wm & 3) * 32 + (lane & 3);     // u32 col base (x4 per mj)
    #pragma unroll
    for (int ni = 0; ni < 2; ni++) {
        int rl = wn * 32 + ni * 16 + (lane >> 2);
        float il = invsm[rl * 2 + half], ih = invsm[(rl + 8) * 2 + half];
        u32* d0 = (u32*)(H + (size_t)(b * HW_ + n0 + rl) * C_) + cu;
        u32* d1 = (u32*)(H + (size_t)(b * HW_ + n0 + rl + 8) * C_) + cu;
        #pragma unroll
        for (int mj = 0; mj < 8; mj++) {
            d0[mj * 4] = pack_h2(C[ni][mj][0] * il, C[ni][mj][1] * il);
            d1[mj * 4] = pack_h2(C[ni][mj][2] * ih, C[ni][mj][3] * ih);
        }
    }
}

// ---------------------------------------------------------------------------
// Attention via fp16 mma.sync: block = 128n x 128m x K=256, 4 chunks of 64
// k-cols, depth-2 double buffer. Pipeline: issue(ch+1) -> compute(ch) ->
// WAIT(0) -> sync  (wait precedes the barrier => cp.async data published).
// ---------------------------------------------------------------------------
#define AT_TILE 18432            // 128 rows x 144 B
#define AT_STG  36864
#define ATTN_SMEM (2 * AT_STG)

__global__ __launch_bounds__(256, 2) void attn_kernel()
{
    extern __shared__ __align__(16) char sm[];
    const u32 smb = smem_u32(sm);
    const int tid = threadIdx.x, lane = tid & 31, wid = tid >> 5;
    const int wn = wid >> 2, wm = wid & 3;
    const int m0 = blockIdx.x * 128, b = blockIdx.y, nz = blockIdx.z;
    const int n0 = nz * 128;

    const char* srcA = (const char*)(g_kh + (size_t)(b * HW_ + n0) * C_);
    const char* srcB = (const char*)(g_qh + (size_t)(b * HW_ + m0) * C_);

    auto load_chunk = [&](int ch, int buf) {
        const u32 dbase = smb + buf * AT_STG;
        #pragma unroll
        for (int it = 0; it < 4; it++) {             // A tile: 1024 segs
            int s = tid + 256 * it;
            int r = s >> 3, q = s & 7;
            CP16(dbase + r * 144 + q * 16, srcA + (u64)r * 512 + ch * 128 + q * 16);
        }
        #pragma unroll
        for (int it = 0; it < 4; it++) {             // B tile
            int s = tid + 256 * it;
            int r = s >> 3, q = s & 7;
            CP16(dbase + AT_TILE + r * 144 + q * 16, srcB + (u64)r * 512 + ch * 128 + q * 16);
        }
        CP_COMMIT();
    };

    const int qq = lane >> 3, rr = lane & 7;
    const u32 aB = smb + (wn * 64 + (qq & 1) * 8 + rr) * 144 + (qq >> 1) * 16;
    const u32 bB = smb + AT_TILE + (wm * 32 + (qq & 1) * 8 + rr) * 144 + (qq >> 1) * 16;

    float C[4][4][4];
    #pragma unroll
    for (int i = 0; i < 4; i++)
        #pragma unroll
        for (int j = 0; j < 4; j++)
            #pragma unroll
            for (int k = 0; k < 4; k++) C[i][j][k] = 0.f;

    float v0[4], v1[4];
    #pragma unroll
    for (int ni = 0; ni < 4; ni++) {
        int nr = n0 + wn * 64 + ni * 16 + (lane >> 2);
        v0[ni] = g_v[b * HW_ + nr];
        v1[ni] = g_v[b * HW_ + nr + 8];
    }

    load_chunk(0, 0);
    CP_WAIT(0);
    __syncthreads();                                 // chunk0 visible to all
    #pragma unroll
    for (int ch = 0; ch < 4; ch++) {
        if (ch < 3) load_chunk(ch + 1, (ch + 1) & 1);   // overlaps compute(ch)

        const int buf = ch & 1;
        const u32 A0 = aB + buf * AT_STG;
        const u32 B0 = bB + buf * AT_STG;
        #pragma unroll
        for (int ks = 0; ks < 4; ks++) {
            u32 ah[4][4], bh[2][4];
            #pragma unroll
            for (int ni = 0; ni < 4; ni++)
                ldmx4(ah[ni], A0 + ks * 32 + ni * 16 * 144);
            #pragma unroll
            for (int p = 0; p < 2; p++)
                ldmx4(bh[p], B0 + ks * 32 + p * 16 * 144);
            #pragma unroll
            for (int ni = 0; ni < 4; ni++)
                #pragma unroll
                for (int mj = 0; mj < 4; mj++) {
                    const int p = mj >> 1, w = mj & 1;
                    mma_f16(C[ni][mj], ah[ni], bh[p][w], bh[p][w + 2]);
                }
        }
        if (ch < 3) { CP_WAIT(0); __syncthreads(); }    // publish chunk ch+1;
                                                        // also fences buf reuse
    }

    float dsum[4][2] = {}, nsum[4][2] = {};
    #pragma unroll
    for (int ni = 0; ni < 4; ni++)
        #pragma unroll
        for (int mj = 0; mj < 4; mj++) {
            float e0 = exp_poly(C[ni][mj][0]);
            float e1 = exp_poly(C[ni][mj][1]);
            float e2 = exp_poly(C[ni][mj][2]);
            float e3 = exp_poly(C[ni][mj][3]);
            dsum[mj][0] += e0 + e2;
            dsum[mj][1] += e1 + e3;
            nsum[mj][0] = fmaf(v0[ni], e0, fmaf(v1[ni], e2, nsum[mj][0]));
            nsum[mj][1] = fmaf(v0[ni], e1, fmaf(v1[ni], e3, nsum[mj][1]));
        }
    #pragma unroll
    for (int mj = 0; mj < 4; mj++)
        #pragma unroll
        for (int h = 0; h < 2; h++) {
            #pragma unroll
            for (int msk = 4; msk <= 16; msk <<= 1) {
                dsum[mj][h] += __shfl_xor_sync(0xFFFFFFFFu, dsum[mj][h], msk);
                nsum[mj][h] += __shfl_xor_sync(0xFFFFFFFFu, nsum[mj][h], msk);
            }
        }

    __syncthreads();
    float* redD = (float*)sm;
    float* redN = redD + 256;
    if (lane < 4) {
        #pragma unroll
        for (int mj = 0; mj < 4; mj++)
            #pragma unroll
            for (int h = 0; h < 2; h++) {
                int col = wm * 32 + mj * 8 + lane * 2 + h;
                redD[wn * 128 + col] = dsum[mj][h];
                redN[wn * 128 + col] = nsum[mj][h];
            }
    }
    __syncthreads();
    if (tid < 128) {
        g_pd[(size_t)(nz * B_ + b) * HW_ + m0 + tid] = redD[tid] + redD[128 + tid];
        g_pn[(size_t)(nz * B_ + b) * HW_ + m0 + tid] = redN[tid] + redN[128 + tid];
    }
}

// ---------------------------------------------------------------------------
// Combine partials: G = sum(num) / sum(den)
// ---------------------------------------------------------------------------
__global__ __launch_bounds__(256) void gfinal_kernel()
{
    int t = blockIdx.x * 256 + threadIdx.x;
    float D = 0.f, N = 0.f;
    #pragma unroll
    for (int z = 0; z < NSPLIT; z++) {
        D += g_pd[z * B_ * HW_ + t];
        N += g_pn[z * B_ * HW_ + t];
    }
    g_G[t] = N / D;
}

// ---------------------------------------------------------------------------
// Conv: out[b,c,i,j] = 3x3 box-sum of G[b,hw]*batch[b,c,hw]
// ---------------------------------------------------------------------------
__global__ __launch_bounds__(256) void conv_kernel(
    const float* __restrict__ batch, float* __restrict__ out)
{
    __shared__ float ys[HW_];
    const int c = blockIdx.x, b = blockIdx.y;
    const float* xb = batch + (b * C_ + c) * HW_;
    const float* Gb = g_G + b * HW_;
    for (int i = threadIdx.x; i < HW_; i += 256) ys[i] = Gb[i] * xb[i];
    __syncthreads();
    float* ob = out + (b * C_ + c) * 900;
    for (int o = threadIdx.x; o < 900; o += 256) {
        int i = o / 30, j = o - i * 30;
        const float* y = ys + i * 32 + j;
        ob[o] = y[0] + y[1] + y[2] +
                y[32] + y[33] + y[34] +
                y[64] + y[65] + y[66];
    }
}

extern "C" void kernel_launch(void* const* d_in, const int* in_sizes, int n_in,
                              void* d_out, int out_size)
{
    const float* batch   = (const float*)d_in[0];
    const float* key_w   = (const float*)d_in[1];
    const float* key_b   = (const float*)d_in[2];
    const float* query_w = (const float*)d_in[3];
    const float* query_b = (const float*)d_in[4];
    const float* value_w = (const float*)d_in[5];
    const float* value_b = (const float*)d_in[6];
    // d_in[7] = local_indices (unused: collapses analytically to 3x3 box filter)

    cudaFuncSetAttribute(proj_kernel, cudaFuncAttributeMaxDynamicSharedMemorySize, PROJ_SMEM);
    cudaFuncSetAttribute(attn_kernel, cudaFuncAttributeMaxDynamicSharedMemorySize, ATTN_SMEM);

    setup_kernel<<<512, 256>>>(key_w, query_w, key_b, query_b);
    proj_kernel<<<dim3(16, 16), 512, PROJ_SMEM>>>(batch, value_w, value_b);
    attn_kernel<<<dim3(8, 16, NSPLIT), 256, ATTN_SMEM>>>();
    gfinal_kernel<<<64, 256>>>();
    conv_kernel<<<dim3(256, 16), 256>>>(batch, (float*)d_out);
}